// round 1
// baseline (speedup 1.0000x reference)
#include <cuda_runtime.h>
#include <cstddef>

constexpr int B_ = 2, N_ = 3072, C_ = 768, H_ = 12, HD_ = 64;
constexpr int M_ = B_ * N_;           // 6144 rows
constexpr int QKVD = 3 * C_;          // 2304

// ---- scratch (static device allocations; no cudaMalloc allowed) ----
__device__ float g_xn[M_ * C_];         // ln output (reused for ln2)
__device__ float g_qkv[M_ * QKVD];      // qkv projections
__device__ float g_attn[M_ * C_];       // attention output (B,N,C layout)
__device__ float g_x1[M_ * C_];         // residual after attention
__device__ float g_h[M_ * 4 * C_];      // MLP hidden

// ============================================================
// LayerNorm: one block per row of 768
// ============================================================
__global__ void ln_kernel(const float* __restrict__ x, const float* __restrict__ g,
                          const float* __restrict__ b, float* __restrict__ out) {
    int row = blockIdx.x;
    int tid = threadIdx.x;
    const float* xr = x + (size_t)row * C_;
    float v[3];
    float s = 0.f, sq = 0.f;
#pragma unroll
    for (int i = 0; i < 3; i++) {
        v[i] = xr[tid + i * 256];
        s += v[i];
        sq += v[i] * v[i];
    }
#pragma unroll
    for (int o = 16; o > 0; o >>= 1) {
        s  += __shfl_xor_sync(0xffffffffu, s, o);
        sq += __shfl_xor_sync(0xffffffffu, sq, o);
    }
    __shared__ float ws[8], wq[8];
    int wid = tid >> 5, lid = tid & 31;
    if (lid == 0) { ws[wid] = s; wq[wid] = sq; }
    __syncthreads();
    if (tid == 0) {
        float ts = 0.f, tq = 0.f;
#pragma unroll
        for (int i = 0; i < 8; i++) { ts += ws[i]; tq += wq[i]; }
        float mean = ts * (1.0f / C_);
        float var  = tq * (1.0f / C_) - mean * mean;
        ws[0] = mean;
        wq[0] = rsqrtf(var + 1e-5f);
    }
    __syncthreads();
    float mean = ws[0], rstd = wq[0];
    float* orow = out + (size_t)row * C_;
#pragma unroll
    for (int i = 0; i < 3; i++) {
        int c = tid + i * 256;
        orow[c] = (v[i] - mean) * rstd * g[c] + b[c];
    }
}

// ============================================================
// SGEMM NT: C[M,Nd] = A[M,K] * W[Nd,K]^T  (+bias, +gelu, +residual)
// Tiles: 128x128x16, 256 threads, 8x8 per thread.
// All dims are exact multiples -> no bounds checks.
// ACT: 0 = none, 1 = exact GELU
// ============================================================
template <int ACT>
__global__ void __launch_bounds__(256, 2)
gemm_nt(const float* __restrict__ A, const float* __restrict__ W,
        const float* __restrict__ bias, const float* __restrict__ resid,
        float* __restrict__ C, int M, int Nd, int K)
{
    constexpr int BM = 128, BN = 128, BK = 16;
    __shared__ __align__(16) float As[BK][BM];
    __shared__ __align__(16) float Bs[BK][BN];
    const int tid = threadIdx.x;
    const int tx = tid & 15, ty = tid >> 4;
    const int m0 = blockIdx.y * BM, n0 = blockIdx.x * BN;

    float acc[8][8];
#pragma unroll
    for (int i = 0; i < 8; i++)
#pragma unroll
        for (int j = 0; j < 8; j++) acc[i][j] = 0.f;

    for (int k0 = 0; k0 < K; k0 += BK) {
        __syncthreads();
#pragma unroll
        for (int i = 0; i < 2; i++) {
            int idx = tid + i * 256;           // 0..511 float4 slots
            int row = idx >> 2, c4 = idx & 3;  // 4 float4 per row
            float4 va = *(const float4*)&A[(size_t)(m0 + row) * K + k0 + c4 * 4];
            As[c4 * 4 + 0][row] = va.x;
            As[c4 * 4 + 1][row] = va.y;
            As[c4 * 4 + 2][row] = va.z;
            As[c4 * 4 + 3][row] = va.w;
            float4 vb = *(const float4*)&W[(size_t)(n0 + row) * K + k0 + c4 * 4];
            Bs[c4 * 4 + 0][row] = vb.x;
            Bs[c4 * 4 + 1][row] = vb.y;
            Bs[c4 * 4 + 2][row] = vb.z;
            Bs[c4 * 4 + 3][row] = vb.w;
        }
        __syncthreads();
#pragma unroll
        for (int k = 0; k < BK; k++) {
            float4 a0 = *(const float4*)&As[k][ty * 8];
            float4 a1 = *(const float4*)&As[k][ty * 8 + 4];
            float4 b0 = *(const float4*)&Bs[k][tx * 8];
            float4 b1 = *(const float4*)&Bs[k][tx * 8 + 4];
            float a[8] = {a0.x, a0.y, a0.z, a0.w, a1.x, a1.y, a1.z, a1.w};
            float bb[8] = {b0.x, b0.y, b0.z, b0.w, b1.x, b1.y, b1.z, b1.w};
#pragma unroll
            for (int i = 0; i < 8; i++)
#pragma unroll
                for (int j = 0; j < 8; j++)
                    acc[i][j] = fmaf(a[i], bb[j], acc[i][j]);
        }
    }

    // epilogue
    float biasv[8];
#pragma unroll
    for (int j = 0; j < 8; j++) biasv[j] = bias ? bias[n0 + tx * 8 + j] : 0.f;

#pragma unroll
    for (int i = 0; i < 8; i++) {
        int m = m0 + ty * 8 + i;
        size_t base = (size_t)m * Nd + n0 + tx * 8;
        float vrow[8];
#pragma unroll
        for (int j = 0; j < 8; j++) {
            float v = acc[i][j] + biasv[j];
            if (ACT == 1) v = 0.5f * v * (1.0f + erff(v * 0.70710678118654752f));
            vrow[j] = v;
        }
        if (resid) {
            float4 r0 = *(const float4*)&resid[base];
            float4 r1 = *(const float4*)&resid[base + 4];
            vrow[0] += r0.x; vrow[1] += r0.y; vrow[2] += r0.z; vrow[3] += r0.w;
            vrow[4] += r1.x; vrow[5] += r1.y; vrow[6] += r1.z; vrow[7] += r1.w;
        }
        *(float4*)&C[base]     = make_float4(vrow[0], vrow[1], vrow[2], vrow[3]);
        *(float4*)&C[base + 4] = make_float4(vrow[4], vrow[5], vrow[6], vrow[7]);
    }
}

// ============================================================
// 2D RoPE applied in-place to q and k of g_qkv.
// qkv layout: [token, which(3), head(12), hd(64)]
// half 0 (dims 0..31) -> y tables, half 1 (dims 32..63) -> x tables.
// Each thread handles one rotation pair (j, j+16) within a half.
// ============================================================
__global__ void rope_kernel(float* __restrict__ qkv,
                            const float* __restrict__ cx, const float* __restrict__ sx,
                            const float* __restrict__ cy, const float* __restrict__ sy)
{
    int t = blockIdx.x * blockDim.x + threadIdx.x;
    int j = t & 15;  t >>= 4;
    int half = t & 1; t >>= 1;
    int h = t % 12;   t /= 12;
    int which = t & 1;
    int tok = t >> 1;                 // 0..M_-1
    if (tok >= M_) return;
    int n = tok % N_;                 // position within the image

    float* p = qkv + (size_t)tok * QKVD + which * C_ + h * HD_ + half * 32;
    const float* ct = half ? cx : cy;
    const float* st = half ? sx : sy;
    float t1 = p[j], t2 = p[j + 16];
    float c1 = ct[n * 32 + j],      s1 = st[n * 32 + j];
    float c2 = ct[n * 32 + j + 16], s2 = st[n * 32 + j + 16];
    p[j]      = t1 * c1 - t2 * s1;
    p[j + 16] = t2 * c2 + t1 * s2;
}

// ============================================================
// Flash attention, fp32. One thread per q row; q,o in registers.
// K/V staged in smem 32 keys at a time. Online softmax.
// grid = (N/128, B*H), block = 128.
// Output layout: [b, n, h*64+d]  (i.e. (B,N,C))
// ============================================================
__global__ void __launch_bounds__(128)
attn_kernel(const float* __restrict__ qkv, float* __restrict__ out)
{
    constexpr int TK = 32;
    __shared__ __align__(16) float4 Ks[TK * 16];
    __shared__ __align__(16) float4 Vs[TK * 16];

    int bh = blockIdx.y;
    int b = bh / H_, h = bh % H_;
    int tid = threadIdx.x;
    int n = blockIdx.x * 128 + tid;

    const float scale = 0.125f;  // HD^-0.5

    size_t qoff = ((size_t)(b * N_ + n)) * QKVD + h * HD_;
    const float4* qp = (const float4*)(qkv + qoff);
    float4 q[16];
#pragma unroll
    for (int i = 0; i < 16; i++) {
        q[i] = qp[i];
        q[i].x *= scale; q[i].y *= scale; q[i].z *= scale; q[i].w *= scale;
    }
    float4 o[16];
#pragma unroll
    for (int i = 0; i < 16; i++) o[i] = make_float4(0.f, 0.f, 0.f, 0.f);
    float mval = -1e30f, l = 0.f;

    size_t kbase = ((size_t)(b * N_)) * QKVD + C_ + h * HD_;       // k section
    size_t vbase = kbase + C_;                                      // v section

    for (int kt = 0; kt < N_; kt += TK) {
        __syncthreads();
#pragma unroll
        for (int i = 0; i < 4; i++) {
            int idx = tid + i * 128;          // 0..511
            int r = idx >> 4, d4 = idx & 15;
            size_t roff = (size_t)(kt + r) * QKVD + d4 * 4;
            Ks[idx] = *(const float4*)(qkv + kbase + roff);
            Vs[idx] = *(const float4*)(qkv + vbase + roff);
        }
        __syncthreads();

        float s[TK];
        float tmax = -1e30f;
#pragma unroll 4
        for (int kk = 0; kk < TK; kk++) {
            float acc = 0.f;
#pragma unroll
            for (int d = 0; d < 16; d++) {
                float4 kv = Ks[kk * 16 + d];
                acc = fmaf(q[d].x, kv.x, acc);
                acc = fmaf(q[d].y, kv.y, acc);
                acc = fmaf(q[d].z, kv.z, acc);
                acc = fmaf(q[d].w, kv.w, acc);
            }
            s[kk] = acc;
            tmax = fmaxf(tmax, acc);
        }
        float newm = fmaxf(mval, tmax);
        float alpha = __expf(mval - newm);
        mval = newm;
        l *= alpha;
#pragma unroll
        for (int i = 0; i < 16; i++) {
            o[i].x *= alpha; o[i].y *= alpha; o[i].z *= alpha; o[i].w *= alpha;
        }
#pragma unroll 4
        for (int kk = 0; kk < TK; kk++) {
            float p = __expf(s[kk] - newm);
            l += p;
#pragma unroll
            for (int d = 0; d < 16; d++) {
                float4 vv = Vs[kk * 16 + d];
                o[d].x = fmaf(p, vv.x, o[d].x);
                o[d].y = fmaf(p, vv.y, o[d].y);
                o[d].z = fmaf(p, vv.z, o[d].z);
                o[d].w = fmaf(p, vv.w, o[d].w);
            }
        }
    }

    float inv = 1.f / l;
    float* op = out + (size_t)(b * N_ + n) * C_ + h * HD_;
#pragma unroll
    for (int i = 0; i < 16; i++) {
        float4 v = o[i];
        v.x *= inv; v.y *= inv; v.z *= inv; v.w *= inv;
        *(float4*)(op + i * 4) = v;
    }
}

// ============================================================
// Launch orchestration
// ============================================================
extern "C" void kernel_launch(void* const* d_in, const int* in_sizes, int n_in,
                              void* d_out, int out_size) {
    const float* x      = (const float*)d_in[0];
    const float* w_qkv  = (const float*)d_in[1];
    const float* w_proj = (const float*)d_in[2];
    const float* b_proj = (const float*)d_in[3];
    const float* g1     = (const float*)d_in[4];
    const float* beta1  = (const float*)d_in[5];
    const float* g2     = (const float*)d_in[6];
    const float* beta2  = (const float*)d_in[7];
    const float* w_fc1  = (const float*)d_in[8];
    const float* b_fc1  = (const float*)d_in[9];
    const float* w_fc2  = (const float*)d_in[10];
    const float* b_fc2  = (const float*)d_in[11];
    const float* cos_x  = (const float*)d_in[12];
    const float* sin_x  = (const float*)d_in[13];
    const float* cos_y  = (const float*)d_in[14];
    const float* sin_y  = (const float*)d_in[15];
    float* out = (float*)d_out;

    float *xn, *qkv, *attn, *x1, *hbuf;
    cudaGetSymbolAddress((void**)&xn,   g_xn);
    cudaGetSymbolAddress((void**)&qkv,  g_qkv);
    cudaGetSymbolAddress((void**)&attn, g_attn);
    cudaGetSymbolAddress((void**)&x1,   g_x1);
    cudaGetSymbolAddress((void**)&hbuf, g_h);

    // 1. LN1
    ln_kernel<<<M_, 256>>>(x, g1, beta1, xn);
    // 2. QKV projection: [6144,768] x [2304,768]^T
    gemm_nt<0><<<dim3(QKVD / 128, M_ / 128), 256>>>(xn, w_qkv, nullptr, nullptr, qkv, M_, QKVD, C_);
    // 3. RoPE on q and k (in place)
    rope_kernel<<<(M_ * 2 * H_ * 2 * 16) / 256, 256>>>(qkv, cos_x, sin_x, cos_y, sin_y);
    // 4. Attention
    attn_kernel<<<dim3(N_ / 128, B_ * H_), 128>>>(qkv, attn);
    // 5. proj + bias + residual(x) -> x1
    gemm_nt<0><<<dim3(C_ / 128, M_ / 128), 256>>>(attn, w_proj, b_proj, x, x1, M_, C_, C_);
    // 6. LN2
    ln_kernel<<<M_, 256>>>(x1, g2, beta2, xn);
    // 7. FC1 + bias + GELU
    gemm_nt<1><<<dim3(4 * C_ / 128, M_ / 128), 256>>>(xn, w_fc1, b_fc1, nullptr, hbuf, M_, 4 * C_, C_);
    // 8. FC2 + bias + residual(x1) -> out
    gemm_nt<0><<<dim3(C_ / 128, M_ / 128), 256>>>(hbuf, w_fc2, b_fc2, x1, out, M_, C_, 4 * C_);
}

// round 2
// speedup vs baseline: 2.9377x; 2.9377x over previous
#include <cuda_runtime.h>
#include <cstdint>
#include <cstddef>

constexpr int B_ = 2, N_ = 3072, C_ = 768, H_ = 12, HD_ = 64;
constexpr int M_ = B_ * N_;           // 6144 rows
constexpr int QKVD = 3 * C_;          // 2304

// ---- scratch (static device allocations; no cudaMalloc allowed) ----
__device__ float g_xn[M_ * C_];         // ln output (reused for ln2)
__device__ float g_qkv[M_ * QKVD];      // qkv projections
__device__ float g_attn[M_ * C_];       // attention output (B,N,C layout)
__device__ float g_x1[M_ * C_];         // residual after attention
__device__ float g_h[M_ * 4 * C_];      // MLP hidden

__device__ __forceinline__ uint32_t f2tf(float f) {
    uint32_t u;
    asm("cvt.rna.tf32.f32 %0, %1;" : "=r"(u) : "f"(f));
    return u;
}

__device__ __forceinline__ void mma_tf32(float* d, const uint32_t* a,
                                         const uint32_t* b, const float* c) {
    asm volatile(
        "mma.sync.aligned.m16n8k8.row.col.f32.tf32.tf32.f32 "
        "{%0,%1,%2,%3},{%4,%5,%6,%7},{%8,%9},{%10,%11,%12,%13};"
        : "=f"(d[0]), "=f"(d[1]), "=f"(d[2]), "=f"(d[3])
        : "r"(a[0]), "r"(a[1]), "r"(a[2]), "r"(a[3]),
          "r"(b[0]), "r"(b[1]),
          "f"(c[0]), "f"(c[1]), "f"(c[2]), "f"(c[3]));
}

// ============================================================
// LayerNorm: one block per row of 768
// ============================================================
__global__ void ln_kernel(const float* __restrict__ x, const float* __restrict__ g,
                          const float* __restrict__ b, float* __restrict__ out) {
    int row = blockIdx.x;
    int tid = threadIdx.x;
    const float* xr = x + (size_t)row * C_;
    float v[3];
    float s = 0.f, sq = 0.f;
#pragma unroll
    for (int i = 0; i < 3; i++) {
        v[i] = xr[tid + i * 256];
        s += v[i];
        sq += v[i] * v[i];
    }
#pragma unroll
    for (int o = 16; o > 0; o >>= 1) {
        s  += __shfl_xor_sync(0xffffffffu, s, o);
        sq += __shfl_xor_sync(0xffffffffu, sq, o);
    }
    __shared__ float ws[8], wq[8];
    int wid = tid >> 5, lid = tid & 31;
    if (lid == 0) { ws[wid] = s; wq[wid] = sq; }
    __syncthreads();
    if (tid == 0) {
        float ts = 0.f, tq = 0.f;
#pragma unroll
        for (int i = 0; i < 8; i++) { ts += ws[i]; tq += wq[i]; }
        float mean = ts * (1.0f / C_);
        float var  = tq * (1.0f / C_) - mean * mean;
        ws[0] = mean;
        wq[0] = rsqrtf(var + 1e-5f);
    }
    __syncthreads();
    float mean = ws[0], rstd = wq[0];
    float* orow = out + (size_t)row * C_;
#pragma unroll
    for (int i = 0; i < 3; i++) {
        int c = tid + i * 256;
        orow[c] = (v[i] - mean) * rstd * g[c] + b[c];
    }
}

// ============================================================
// tf32 tensor-core GEMM NT: C[M,Nd] = A[M,K] * W[Nd,K]^T (+bias,+gelu,+resid)
// 128x128x16 tiles, 8 warps (2x4), warp tile 64x32, mma m16n8k8.
// Smem padded stride 20 -> conflict-free fragment LDS.
// ============================================================
template <int ACT>
__global__ void __launch_bounds__(256)
gemm_tf32(const float* __restrict__ A, const float* __restrict__ W,
          const float* __restrict__ bias, const float* __restrict__ resid,
          float* __restrict__ C, int M, int Nd, int K)
{
    constexpr int PAD = 20;
    __shared__ uint32_t As[2][128 * PAD];
    __shared__ uint32_t Ws[2][128 * PAD];

    const int tid = threadIdx.x;
    const int lane = tid & 31;
    const int wid = tid >> 5;
    const int warpM = wid >> 2, warpN = wid & 3;
    const int g = lane >> 2, q = lane & 3;
    const int m0 = blockIdx.y * 128, n0 = blockIdx.x * 128;

    float acc[4][4][4];
#pragma unroll
    for (int mt = 0; mt < 4; mt++)
#pragma unroll
        for (int nt = 0; nt < 4; nt++)
#pragma unroll
            for (int r = 0; r < 4; r++) acc[mt][nt][r] = 0.f;

    const int j0 = tid, j1 = tid + 256;
    const int r0 = j0 >> 2, c0 = (j0 & 3) * 4;
    const int r1 = j1 >> 2, c1 = (j1 & 3) * 4;

    float4 pa0, pa1, pw0, pw1;
    auto ldg = [&](int k0) {
        pa0 = *(const float4*)&A[(size_t)(m0 + r0) * K + k0 + c0];
        pa1 = *(const float4*)&A[(size_t)(m0 + r1) * K + k0 + c1];
        pw0 = *(const float4*)&W[(size_t)(n0 + r0) * K + k0 + c0];
        pw1 = *(const float4*)&W[(size_t)(n0 + r1) * K + k0 + c1];
    };
    auto sts = [&](int buf) {
        uint32_t* a0p = &As[buf][r0 * PAD + c0];
        a0p[0] = f2tf(pa0.x); a0p[1] = f2tf(pa0.y); a0p[2] = f2tf(pa0.z); a0p[3] = f2tf(pa0.w);
        uint32_t* a1p = &As[buf][r1 * PAD + c1];
        a1p[0] = f2tf(pa1.x); a1p[1] = f2tf(pa1.y); a1p[2] = f2tf(pa1.z); a1p[3] = f2tf(pa1.w);
        uint32_t* w0p = &Ws[buf][r0 * PAD + c0];
        w0p[0] = f2tf(pw0.x); w0p[1] = f2tf(pw0.y); w0p[2] = f2tf(pw0.z); w0p[3] = f2tf(pw0.w);
        uint32_t* w1p = &Ws[buf][r1 * PAD + c1];
        w1p[0] = f2tf(pw1.x); w1p[1] = f2tf(pw1.y); w1p[2] = f2tf(pw1.z); w1p[3] = f2tf(pw1.w);
    };

    const int T = K / 16;
    ldg(0);
    sts(0);
    __syncthreads();

    for (int t = 0; t < T; t++) {
        if (t + 1 < T) ldg((t + 1) * 16);
        int buf = t & 1;
#pragma unroll
        for (int ks = 0; ks < 2; ks++) {
            uint32_t af[4][4];
#pragma unroll
            for (int mt = 0; mt < 4; mt++) {
                int rr = warpM * 64 + mt * 16 + g;
                int kc = ks * 8 + q;
                af[mt][0] = As[buf][rr * PAD + kc];
                af[mt][1] = As[buf][(rr + 8) * PAD + kc];
                af[mt][2] = As[buf][rr * PAD + kc + 4];
                af[mt][3] = As[buf][(rr + 8) * PAD + kc + 4];
            }
            uint32_t bf[4][2];
#pragma unroll
            for (int nt = 0; nt < 4; nt++) {
                int cc = warpN * 32 + nt * 8 + g;
                int kc = ks * 8 + q;
                bf[nt][0] = Ws[buf][cc * PAD + kc];
                bf[nt][1] = Ws[buf][cc * PAD + kc + 4];
            }
#pragma unroll
            for (int mt = 0; mt < 4; mt++)
#pragma unroll
                for (int nt = 0; nt < 4; nt++)
                    mma_tf32(acc[mt][nt], af[mt], bf[nt], acc[mt][nt]);
        }
        if (t + 1 < T) {
            sts((t + 1) & 1);
            __syncthreads();
        }
    }

    // epilogue
#pragma unroll
    for (int mt = 0; mt < 4; mt++) {
#pragma unroll
        for (int nt = 0; nt < 4; nt++) {
            int m = m0 + warpM * 64 + mt * 16 + g;
            int cc = n0 + warpN * 32 + nt * 8 + 2 * q;
            float bv0 = 0.f, bv1 = 0.f;
            if (bias) { bv0 = bias[cc]; bv1 = bias[cc + 1]; }
            float v[4];
            v[0] = acc[mt][nt][0] + bv0;
            v[1] = acc[mt][nt][1] + bv1;
            v[2] = acc[mt][nt][2] + bv0;
            v[3] = acc[mt][nt][3] + bv1;
            if (ACT == 1) {
#pragma unroll
                for (int r = 0; r < 4; r++)
                    v[r] = 0.5f * v[r] * (1.0f + erff(v[r] * 0.70710678118654752f));
            }
            size_t base0 = (size_t)m * Nd + cc;
            size_t base1 = (size_t)(m + 8) * Nd + cc;
            if (resid) {
                float2 rr0 = *(const float2*)&resid[base0];
                float2 rr1 = *(const float2*)&resid[base1];
                v[0] += rr0.x; v[1] += rr0.y;
                v[2] += rr1.x; v[3] += rr1.y;
            }
            *(float2*)&C[base0] = make_float2(v[0], v[1]);
            *(float2*)&C[base1] = make_float2(v[2], v[3]);
        }
    }
}

// ============================================================
// 2D RoPE applied in-place to q and k of g_qkv.
// ============================================================
__global__ void rope_kernel(float* __restrict__ qkv,
                            const float* __restrict__ cx, const float* __restrict__ sx,
                            const float* __restrict__ cy, const float* __restrict__ sy)
{
    int t = blockIdx.x * blockDim.x + threadIdx.x;
    int j = t & 15;  t >>= 4;
    int half = t & 1; t >>= 1;
    int h = t % 12;   t /= 12;
    int which = t & 1;
    int tok = t >> 1;
    if (tok >= M_) return;
    int n = tok % N_;

    float* p = qkv + (size_t)tok * QKVD + which * C_ + h * HD_ + half * 32;
    const float* ct = half ? cx : cy;
    const float* st = half ? sx : sy;
    float t1 = p[j], t2 = p[j + 16];
    float c1 = ct[n * 32 + j],      s1 = st[n * 32 + j];
    float c2 = ct[n * 32 + j + 16], s2 = st[n * 32 + j + 16];
    p[j]      = t1 * c1 - t2 * s1;
    p[j + 16] = t2 * c2 + t1 * s2;
}

// ============================================================
// Flash attention with tf32 mma.
// grid (N/64, B*H), block 128 (4 warps). Each warp: 16 q rows.
// smem (dynamic): Ks[64][68], Vs[64][72], Ps[64][68]  (tf32 uints)
// ============================================================
constexpr int KS_STRIDE = 68;   // (4g+q) pattern -> conflict free for K^T B-frags
constexpr int VS_STRIDE = 72;   // (8q+g) pattern -> conflict free for V B-frags
constexpr int PS_STRIDE = 68;
constexpr int SMEM_ATTN = (64 * KS_STRIDE + 64 * VS_STRIDE + 64 * PS_STRIDE) * 4;

__global__ void __launch_bounds__(128)
attn_tf32(const float* __restrict__ qkv, float* __restrict__ out)
{
    extern __shared__ uint32_t sm[];
    uint32_t* Ks = sm;
    uint32_t* Vs = Ks + 64 * KS_STRIDE;
    uint32_t* Ps = Vs + 64 * VS_STRIDE;

    const int tid = threadIdx.x;
    const int lane = tid & 31;
    const int wid = tid >> 5;
    const int g = lane >> 2, q = lane & 3;
    const int bh = blockIdx.y;
    const int b = bh / H_, h = bh % H_;
    const int qrow = blockIdx.x * 64 + wid * 16 + g;   // this thread's q row (and +8)
    const float scale = 0.125f;

    // Q fragments (scaled, tf32)
    uint32_t qf[8][4];
    {
        const float* q0 = qkv + (size_t)(b * N_ + qrow) * QKVD + h * HD_;
        const float* q1 = q0 + 8 * QKVD;
#pragma unroll
        for (int ks = 0; ks < 8; ks++) {
            int col = ks * 8 + q;
            qf[ks][0] = f2tf(q0[col] * scale);
            qf[ks][1] = f2tf(q1[col] * scale);
            qf[ks][2] = f2tf(q0[col + 4] * scale);
            qf[ks][3] = f2tf(q1[col + 4] * scale);
        }
    }

    float o[8][4];
#pragma unroll
    for (int nt = 0; nt < 8; nt++)
#pragma unroll
        for (int r = 0; r < 4; r++) o[nt][r] = 0.f;
    float m0v = -1e30f, m1v = -1e30f, l0 = 0.f, l1 = 0.f;

    const size_t kgbase = (size_t)(b * N_) * QKVD + C_ + h * HD_;
    const size_t vgbase = kgbase + C_;

    for (int kt = 0; kt < N_; kt += 64) {
        __syncthreads();
        // stage K/V tiles (64x64) into smem as tf32
#pragma unroll
        for (int i = 0; i < 8; i++) {
            int j = tid + i * 128;          // 0..1023 float4 slots
            int row = j >> 4, c4 = (j & 15) * 4;
            size_t roff = (size_t)(kt + row) * QKVD + c4;
            float4 kv = *(const float4*)(qkv + kgbase + roff);
            uint32_t* kp = &Ks[row * KS_STRIDE + c4];
            kp[0] = f2tf(kv.x); kp[1] = f2tf(kv.y); kp[2] = f2tf(kv.z); kp[3] = f2tf(kv.w);
            float4 vv = *(const float4*)(qkv + vgbase + roff);
            uint32_t* vp = &Vs[row * VS_STRIDE + c4];
            vp[0] = f2tf(vv.x); vp[1] = f2tf(vv.y); vp[2] = f2tf(vv.z); vp[3] = f2tf(vv.w);
        }
        __syncthreads();

        // S = Q K^T  (16 x 64 per warp)
        float s[8][4];
#pragma unroll
        for (int nt = 0; nt < 8; nt++)
#pragma unroll
            for (int r = 0; r < 4; r++) s[nt][r] = 0.f;
#pragma unroll
        for (int ks = 0; ks < 8; ks++) {
            int kc = ks * 8 + q;
#pragma unroll
            for (int nt = 0; nt < 8; nt++) {
                uint32_t bf[2];
                bf[0] = Ks[(nt * 8 + g) * KS_STRIDE + kc];
                bf[1] = Ks[(nt * 8 + g) * KS_STRIDE + kc + 4];
                mma_tf32(s[nt], qf[ks], bf, s[nt]);
            }
        }

        // online softmax (rows r=qrow via regs 0,1 ; row qrow+8 via regs 2,3)
        float mx0 = -1e30f, mx1 = -1e30f;
#pragma unroll
        for (int nt = 0; nt < 8; nt++) {
            mx0 = fmaxf(mx0, fmaxf(s[nt][0], s[nt][1]));
            mx1 = fmaxf(mx1, fmaxf(s[nt][2], s[nt][3]));
        }
        mx0 = fmaxf(mx0, __shfl_xor_sync(0xffffffffu, mx0, 1));
        mx0 = fmaxf(mx0, __shfl_xor_sync(0xffffffffu, mx0, 2));
        mx1 = fmaxf(mx1, __shfl_xor_sync(0xffffffffu, mx1, 1));
        mx1 = fmaxf(mx1, __shfl_xor_sync(0xffffffffu, mx1, 2));

        float nm0 = fmaxf(m0v, mx0), nm1 = fmaxf(m1v, mx1);
        float a0 = __expf(m0v - nm0), a1 = __expf(m1v - nm1);
        m0v = nm0; m1v = nm1;
        l0 *= a0; l1 *= a1;
#pragma unroll
        for (int nt = 0; nt < 8; nt++) {
            o[nt][0] *= a0; o[nt][1] *= a0;
            o[nt][2] *= a1; o[nt][3] *= a1;
        }

        float ps0 = 0.f, ps1 = 0.f;
        uint32_t* prow0 = &Ps[(wid * 16 + g) * PS_STRIDE];
        uint32_t* prow1 = &Ps[(wid * 16 + g + 8) * PS_STRIDE];
#pragma unroll
        for (int nt = 0; nt < 8; nt++) {
            float p0 = __expf(s[nt][0] - nm0);
            float p1 = __expf(s[nt][1] - nm0);
            float p2 = __expf(s[nt][2] - nm1);
            float p3 = __expf(s[nt][3] - nm1);
            ps0 += p0 + p1;
            ps1 += p2 + p3;
            int cc = nt * 8 + 2 * q;
            prow0[cc] = f2tf(p0); prow0[cc + 1] = f2tf(p1);
            prow1[cc] = f2tf(p2); prow1[cc + 1] = f2tf(p3);
        }
        ps0 += __shfl_xor_sync(0xffffffffu, ps0, 1);
        ps0 += __shfl_xor_sync(0xffffffffu, ps0, 2);
        ps1 += __shfl_xor_sync(0xffffffffu, ps1, 1);
        ps1 += __shfl_xor_sync(0xffffffffu, ps1, 2);
        l0 += ps0; l1 += ps1;

        __syncwarp();

        // O += P V
#pragma unroll
        for (int ks = 0; ks < 8; ks++) {
            int kc = ks * 8 + q;
            uint32_t af[4];
            af[0] = Ps[(wid * 16 + g) * PS_STRIDE + kc];
            af[1] = Ps[(wid * 16 + g + 8) * PS_STRIDE + kc];
            af[2] = Ps[(wid * 16 + g) * PS_STRIDE + kc + 4];
            af[3] = Ps[(wid * 16 + g + 8) * PS_STRIDE + kc + 4];
#pragma unroll
            for (int nt = 0; nt < 8; nt++) {
                uint32_t bf[2];
                bf[0] = Vs[(ks * 8 + q) * VS_STRIDE + nt * 8 + g];
                bf[1] = Vs[(ks * 8 + q + 4) * VS_STRIDE + nt * 8 + g];
                mma_tf32(o[nt], af, bf, o[nt]);
            }
        }
        __syncwarp();
    }

    float inv0 = 1.f / l0, inv1 = 1.f / l1;
    float* orow0 = out + (size_t)(b * N_ + qrow) * C_ + h * HD_;
    float* orow1 = orow0 + (size_t)8 * C_;
#pragma unroll
    for (int nt = 0; nt < 8; nt++) {
        int cc = nt * 8 + 2 * q;
        *(float2*)&orow0[cc] = make_float2(o[nt][0] * inv0, o[nt][1] * inv0);
        *(float2*)&orow1[cc] = make_float2(o[nt][2] * inv1, o[nt][3] * inv1);
    }
}

// ============================================================
// Launch orchestration
// ============================================================
extern "C" void kernel_launch(void* const* d_in, const int* in_sizes, int n_in,
                              void* d_out, int out_size) {
    const float* x      = (const float*)d_in[0];
    const float* w_qkv  = (const float*)d_in[1];
    const float* w_proj = (const float*)d_in[2];
    const float* b_proj = (const float*)d_in[3];
    const float* g1     = (const float*)d_in[4];
    const float* beta1  = (const float*)d_in[5];
    const float* g2     = (const float*)d_in[6];
    const float* beta2  = (const float*)d_in[7];
    const float* w_fc1  = (const float*)d_in[8];
    const float* b_fc1  = (const float*)d_in[9];
    const float* w_fc2  = (const float*)d_in[10];
    const float* b_fc2  = (const float*)d_in[11];
    const float* cos_x  = (const float*)d_in[12];
    const float* sin_x  = (const float*)d_in[13];
    const float* cos_y  = (const float*)d_in[14];
    const float* sin_y  = (const float*)d_in[15];
    float* out = (float*)d_out;

    float *xn, *qkv, *attn, *x1, *hbuf;
    cudaGetSymbolAddress((void**)&xn,   g_xn);
    cudaGetSymbolAddress((void**)&qkv,  g_qkv);
    cudaGetSymbolAddress((void**)&attn, g_attn);
    cudaGetSymbolAddress((void**)&x1,   g_x1);
    cudaGetSymbolAddress((void**)&hbuf, g_h);

    cudaFuncSetAttribute(attn_tf32, cudaFuncAttributeMaxDynamicSharedMemorySize, SMEM_ATTN);

    // 1. LN1
    ln_kernel<<<M_, 256>>>(x, g1, beta1, xn);
    // 2. QKV projection
    gemm_tf32<0><<<dim3(QKVD / 128, M_ / 128), 256>>>(xn, w_qkv, nullptr, nullptr, qkv, M_, QKVD, C_);
    // 3. RoPE on q and k (in place)
    rope_kernel<<<(M_ * 2 * H_ * 2 * 16) / 256, 256>>>(qkv, cos_x, sin_x, cos_y, sin_y);
    // 4. Attention (tensor cores)
    attn_tf32<<<dim3(N_ / 64, B_ * H_), 128, SMEM_ATTN>>>(qkv, attn);
    // 5. proj + bias + residual(x) -> x1
    gemm_tf32<0><<<dim3(C_ / 128, M_ / 128), 256>>>(attn, w_proj, b_proj, x, x1, M_, C_, C_);
    // 6. LN2
    ln_kernel<<<M_, 256>>>(x1, g2, beta2, xn);
    // 7. FC1 + bias + GELU
    gemm_tf32<1><<<dim3(4 * C_ / 128, M_ / 128), 256>>>(xn, w_fc1, b_fc1, nullptr, hbuf, M_, 4 * C_, C_);
    // 8. FC2 + bias + residual(x1) -> out
    gemm_tf32<0><<<dim3(C_ / 128, M_ / 128), 256>>>(hbuf, w_fc2, b_fc2, x1, out, M_, C_, 4 * C_);
}

// round 3
// speedup vs baseline: 6.3501x; 2.1616x over previous
#include <cuda_runtime.h>
#include <cuda_fp16.h>
#include <cstdint>
#include <cstddef>

constexpr int B_ = 2, N_ = 3072, C_ = 768, H_ = 12, HD_ = 64;
constexpr int M_ = B_ * N_;           // 6144
constexpr int QKVD = 3 * C_;          // 2304

// ---- static scratch ----
__device__ __half g_xnh[M_ * C_];
__device__ __half g_qkvh[(size_t)M_ * QKVD];
__device__ __half g_attnh[M_ * C_];
__device__ float  g_x1[M_ * C_];
__device__ __half g_hh[(size_t)M_ * 4 * C_];
__device__ half2  g_vt[(size_t)B_ * H_ * (N_ / 2) * HD_];   // [bh][keypair][dim]
__device__ __half g_wqkvh[QKVD * C_];
__device__ __half g_wprojh[C_ * C_];
__device__ __half g_wfc1h[4 * C_ * C_];
__device__ __half g_wfc2h[C_ * 4 * C_];

// ---- ptx helpers ----
__device__ __forceinline__ void mma_f16(float* d, const uint32_t* a,
                                        const uint32_t* b, const float* c) {
    asm volatile(
        "mma.sync.aligned.m16n8k16.row.col.f32.f16.f16.f32 "
        "{%0,%1,%2,%3},{%4,%5,%6,%7},{%8,%9},{%10,%11,%12,%13};"
        : "=f"(d[0]), "=f"(d[1]), "=f"(d[2]), "=f"(d[3])
        : "r"(a[0]), "r"(a[1]), "r"(a[2]), "r"(a[3]),
          "r"(b[0]), "r"(b[1]),
          "f"(c[0]), "f"(c[1]), "f"(c[2]), "f"(c[3]));
}
__device__ __forceinline__ void ldsm4(uint32_t* r, uint32_t a) {
    asm volatile("ldmatrix.sync.aligned.m8n8.x4.shared.b16 {%0,%1,%2,%3}, [%4];"
                 : "=r"(r[0]), "=r"(r[1]), "=r"(r[2]), "=r"(r[3]) : "r"(a));
}
__device__ __forceinline__ void cpa16(uint32_t dst, const void* src) {
    asm volatile("cp.async.cg.shared.global [%0], [%1], 16;\n" :: "r"(dst), "l"(src));
}
#define CP_COMMIT() asm volatile("cp.async.commit_group;\n" ::: "memory")
#define CP_WAIT1()  asm volatile("cp.async.wait_group 1;\n" ::: "memory")

__device__ __forceinline__ uint32_t h2u(half2 h) { return *(uint32_t*)&h; }

// ============================================================
// fp32 -> fp16 conversion (8 elems/thread)
// ============================================================
__global__ void f2h_kernel(const float* __restrict__ s, __half* __restrict__ d, int n8) {
    int i = blockIdx.x * blockDim.x + threadIdx.x;
    if (i >= n8) return;
    const float4* sp = (const float4*)s;
    float4 a = sp[2 * i], b = sp[2 * i + 1];
    half2 h[4] = {__floats2half2_rn(a.x, a.y), __floats2half2_rn(a.z, a.w),
                  __floats2half2_rn(b.x, b.y), __floats2half2_rn(b.z, b.w)};
    ((uint4*)d)[i] = *(uint4*)h;
}

// ============================================================
// LayerNorm -> half output
// ============================================================
__global__ void ln_h(const float* __restrict__ x, const float* __restrict__ g,
                     const float* __restrict__ b, __half* __restrict__ out) {
    int row = blockIdx.x;
    int tid = threadIdx.x;
    const float* xr = x + (size_t)row * C_;
    float v[3];
    float s = 0.f, sq = 0.f;
#pragma unroll
    for (int i = 0; i < 3; i++) {
        v[i] = xr[tid + i * 256];
        s += v[i];
        sq += v[i] * v[i];
    }
#pragma unroll
    for (int o = 16; o > 0; o >>= 1) {
        s  += __shfl_xor_sync(0xffffffffu, s, o);
        sq += __shfl_xor_sync(0xffffffffu, sq, o);
    }
    __shared__ float ws[8], wq[8];
    int wid = tid >> 5, lid = tid & 31;
    if (lid == 0) { ws[wid] = s; wq[wid] = sq; }
    __syncthreads();
    if (tid == 0) {
        float ts = 0.f, tq = 0.f;
#pragma unroll
        for (int i = 0; i < 8; i++) { ts += ws[i]; tq += wq[i]; }
        float mean = ts * (1.0f / C_);
        float var  = tq * (1.0f / C_) - mean * mean;
        ws[0] = mean;
        wq[0] = rsqrtf(var + 1e-5f);
    }
    __syncthreads();
    float mean = ws[0], rstd = wq[0];
    __half* orow = out + (size_t)row * C_;
#pragma unroll
    for (int i = 0; i < 3; i++) {
        int c = tid + i * 256;
        orow[c] = __float2half_rn((v[i] - mean) * rstd * g[c] + b[c]);
    }
}

// ============================================================
// fp16 tensor-core GEMM NT: C[M,Nd] = A[M,K] * W[Nd,K]^T
// 128x128x32 tiles, 8 warps, 3-stage cp.async, ldmatrix A frags.
// ============================================================
constexpr int ASTR = 40;                   // halves per smem row (pad 8)
constexpr int GSTG = 128 * ASTR;           // halves per stage per matrix
constexpr int SMEM_GEMM = 2 * 3 * GSTG * 2;  // bytes

template <int ACT, int OUTH>
__global__ void __launch_bounds__(256)
gemm_h(const __half* __restrict__ A, const __half* __restrict__ W,
       const float* __restrict__ bias, const float* __restrict__ resid,
       void* __restrict__ Cout, int M, int Nd, int K)
{
    extern __shared__ __half sm[];
    __half* As = sm;
    __half* Ws = sm + 3 * GSTG;

    const int tid = threadIdx.x, lane = tid & 31, wid = tid >> 5;
    const int warpM = wid >> 2, warpN = wid & 3;
    const int g = lane >> 2, q = lane & 3;
    const int m0 = blockIdx.y * 128, n0 = blockIdx.x * 128;

    const uint32_t asbase = (uint32_t)__cvta_generic_to_shared(As);
    const uint32_t wsbase = (uint32_t)__cvta_generic_to_shared(Ws);

    const int ar0 = tid >> 2,           ac0 = (tid & 3) * 8;
    const int ar1 = (tid + 256) >> 2,   ac1 = ((tid + 256) & 3) * 8;

    auto stage = [&](int t, int s) {
        int k0 = t * 32;
        uint32_t ab = asbase + s * (GSTG * 2);
        uint32_t wb = wsbase + s * (GSTG * 2);
        cpa16(ab + (ar0 * ASTR + ac0) * 2, A + (size_t)(m0 + ar0) * K + k0 + ac0);
        cpa16(ab + (ar1 * ASTR + ac1) * 2, A + (size_t)(m0 + ar1) * K + k0 + ac1);
        cpa16(wb + (ar0 * ASTR + ac0) * 2, W + (size_t)(n0 + ar0) * K + k0 + ac0);
        cpa16(wb + (ar1 * ASTR + ac1) * 2, W + (size_t)(n0 + ar1) * K + k0 + ac1);
    };

    float acc[4][4][4];
#pragma unroll
    for (int mt = 0; mt < 4; mt++)
#pragma unroll
        for (int nt = 0; nt < 4; nt++)
#pragma unroll
            for (int r = 0; r < 4; r++) acc[mt][nt][r] = 0.f;

    const int T = K / 32;
    stage(0, 0); CP_COMMIT();
    stage(1, 1); CP_COMMIT();

    const int lrow = warpM * 64 + (lane & 7) + ((lane >> 3) & 1) * 8;
    const int lcol = (lane >> 4) * 8;

    for (int t = 0; t < T; t++) {
        CP_WAIT1();
        __syncthreads();
        if (t + 2 < T) stage(t + 2, (t + 2) % 3);
        CP_COMMIT();
        const int s = t % 3;
        const __half* Wb = Ws + s * GSTG;
        const uint32_t ab = asbase + s * (GSTG * 2);
#pragma unroll
        for (int kk = 0; kk < 32; kk += 16) {
            uint32_t af[4][4];
#pragma unroll
            for (int mt = 0; mt < 4; mt++)
                ldsm4(af[mt], ab + ((lrow + mt * 16) * ASTR + lcol + kk) * 2);
            uint32_t bf[4][2];
#pragma unroll
            for (int nt = 0; nt < 4; nt++) {
                const __half* wp = Wb + (warpN * 32 + nt * 8 + g) * ASTR + kk + 2 * q;
                bf[nt][0] = *(const uint32_t*)wp;
                bf[nt][1] = *(const uint32_t*)(wp + 8);
            }
#pragma unroll
            for (int mt = 0; mt < 4; mt++)
#pragma unroll
                for (int nt = 0; nt < 4; nt++)
                    mma_f16(acc[mt][nt], af[mt], bf[nt], acc[mt][nt]);
        }
    }

    // epilogue
#pragma unroll
    for (int mt = 0; mt < 4; mt++) {
#pragma unroll
        for (int nt = 0; nt < 4; nt++) {
            int m = m0 + warpM * 64 + mt * 16 + g;
            int c = n0 + warpN * 32 + nt * 8 + 2 * q;
            float bv0 = bias ? bias[c] : 0.f;
            float bv1 = bias ? bias[c + 1] : 0.f;
            float v0 = acc[mt][nt][0] + bv0, v1 = acc[mt][nt][1] + bv1;
            float v2 = acc[mt][nt][2] + bv0, v3 = acc[mt][nt][3] + bv1;
            if (ACT == 1) {
                v0 = 0.5f * v0 * (1.0f + erff(v0 * 0.70710678118654752f));
                v1 = 0.5f * v1 * (1.0f + erff(v1 * 0.70710678118654752f));
                v2 = 0.5f * v2 * (1.0f + erff(v2 * 0.70710678118654752f));
                v3 = 0.5f * v3 * (1.0f + erff(v3 * 0.70710678118654752f));
            }
            size_t i0 = (size_t)m * Nd + c, i1 = (size_t)(m + 8) * Nd + c;
            if (OUTH) {
                __half* O = (__half*)Cout;
                *(half2*)(O + i0) = __floats2half2_rn(v0, v1);
                *(half2*)(O + i1) = __floats2half2_rn(v2, v3);
            } else {
                float* O = (float*)Cout;
                if (resid) {
                    float2 r0 = *(const float2*)&resid[i0];
                    float2 r1 = *(const float2*)&resid[i1];
                    v0 += r0.x; v1 += r0.y; v2 += r1.x; v3 += r1.y;
                }
                *(float2*)&O[i0] = make_float2(v0, v1);
                *(float2*)&O[i1] = make_float2(v2, v3);
            }
        }
    }
}

// ============================================================
// 2D RoPE in place on half qkv (q and k sections)
// ============================================================
__global__ void rope_h(__half* __restrict__ qkv,
                       const float* __restrict__ cx, const float* __restrict__ sx,
                       const float* __restrict__ cy, const float* __restrict__ sy)
{
    int t = blockIdx.x * blockDim.x + threadIdx.x;
    int j = t & 15;  t >>= 4;
    int half_ = t & 1; t >>= 1;
    int h = t % 12;   t /= 12;
    int which = t & 1;
    int tok = t >> 1;
    if (tok >= M_) return;
    int n = tok % N_;

    __half* p = qkv + (size_t)tok * QKVD + which * C_ + h * HD_ + half_ * 32;
    const float* ct = half_ ? cx : cy;
    const float* st = half_ ? sx : sy;
    float t1 = __half2float(p[j]), t2 = __half2float(p[j + 16]);
    float c1 = ct[n * 32 + j],      s1 = st[n * 32 + j];
    float c2 = ct[n * 32 + j + 16], s2 = st[n * 32 + j + 16];
    p[j]      = __float2half_rn(t1 * c1 - t2 * s1);
    p[j + 16] = __float2half_rn(t2 * c2 + t1 * s2);
}

// ============================================================
// V transpose-pack: qkv v-section -> g_vt[bh][keypair][dim] half2
// ============================================================
__global__ void vpack(const __half* __restrict__ qkvh, half2* __restrict__ vt) {
    int t = blockIdx.x * blockDim.x + threadIdx.x;   // 24*1536*8
    int d8 = t & 7;
    int pr = (t >> 3) % (N_ / 2);
    int bh = t / (8 * (N_ / 2));
    if (bh >= B_ * H_) return;
    int b = bh / H_, h = bh % H_;
    const __half* s0 = qkvh + (size_t)(b * N_ + 2 * pr) * QKVD + 2 * C_ + h * HD_ + d8 * 8;
    const __half* s1 = s0 + QKVD;
    __half a0[8], a1[8];
    *(uint4*)a0 = *(const uint4*)s0;
    *(uint4*)a1 = *(const uint4*)s1;
    half2 o[8];
#pragma unroll
    for (int i = 0; i < 8; i++) o[i] = __halves2half2(a0[i], a1[i]);
    half2* dst = vt + ((size_t)bh * (N_ / 2) + pr) * HD_ + d8 * 8;
    *(uint4*)dst = *(uint4*)o;
    *(uint4*)(dst + 4) = *(uint4*)(o + 4);
}

// ============================================================
// Flash attention fp16 mma, double-buffered cp.async K/V tiles.
// grid (N/64, B*H), 128 threads (4 warps, 16 q-rows each).
// ============================================================
constexpr int KSTR = 72;   // halves per K smem row (144B) -> conflict-free
constexpr int VSTR = 72;   // half2 per V smem row (288B) -> conflict-free

__global__ void __launch_bounds__(128)
attn_h(const __half* __restrict__ qkvh, const half2* __restrict__ vt,
       __half* __restrict__ outh)
{
    __shared__ __half Ks[2][64 * KSTR];
    __shared__ half2  Vp[2][32 * VSTR];

    const int tid = threadIdx.x, lane = tid & 31, wid = tid >> 5;
    const int g = lane >> 2, q = lane & 3;
    const int bh = blockIdx.y, b = bh / H_, h = bh % H_;
    const int qrow = blockIdx.x * 64 + wid * 16 + g;

    const uint32_t ksbase = (uint32_t)__cvta_generic_to_shared(&Ks[0][0]);
    const uint32_t vpbase = (uint32_t)__cvta_generic_to_shared(&Vp[0][0]);

    // Q fragments (x 0.125 exact in fp16)
    uint32_t qf[4][4];
    {
        const __half* q0 = qkvh + (size_t)(b * N_ + qrow) * QKVD + h * HD_;
        const __half* q1 = q0 + (size_t)8 * QKVD;
        const half2 sc = __float2half2_rn(0.125f);
#pragma unroll
        for (int ks = 0; ks < 4; ks++) {
            int col = ks * 16 + 2 * q;
            half2 a0 = __hmul2(*(const half2*)(q0 + col), sc);
            half2 a1 = __hmul2(*(const half2*)(q1 + col), sc);
            half2 a2 = __hmul2(*(const half2*)(q0 + col + 8), sc);
            half2 a3 = __hmul2(*(const half2*)(q1 + col + 8), sc);
            qf[ks][0] = h2u(a0); qf[ks][1] = h2u(a1);
            qf[ks][2] = h2u(a2); qf[ks][3] = h2u(a3);
        }
    }

    const size_t kgbase = (size_t)(b * N_) * QKVD + C_ + h * HD_;
    const half2* vbh = vt + (size_t)bh * (N_ / 2) * HD_;

    auto stage = [&](int kt, int buf) {
#pragma unroll
        for (int i = 0; i < 4; i++) {
            int idx = tid + i * 128;
            int r = idx >> 3, c = idx & 7;
            cpa16(ksbase + (buf * 64 * KSTR + r * KSTR + c * 8) * 2,
                  qkvh + kgbase + (size_t)(kt + r) * QKVD + c * 8);
        }
        const half2* vsrc = vbh + (size_t)(kt >> 1) * HD_;
#pragma unroll
        for (int i = 0; i < 4; i++) {
            int idx = tid + i * 128;
            int r = idx >> 4, c = idx & 15;
            cpa16(vpbase + (buf * 32 * VSTR + r * VSTR + c * 4) * 4,
                  vsrc + r * HD_ + c * 4);
        }
    };

    float o[8][4];
#pragma unroll
    for (int nt = 0; nt < 8; nt++)
#pragma unroll
        for (int r = 0; r < 4; r++) o[nt][r] = 0.f;
    float m0v = -1e30f, m1v = -1e30f, l0 = 0.f, l1 = 0.f;

    stage(0, 0); CP_COMMIT();

    constexpr int T = N_ / 64;   // 48
    for (int t = 0; t < T; t++) {
        if (t + 1 < T) stage((t + 1) * 64, (t + 1) & 1);
        CP_COMMIT();
        CP_WAIT1();
        __syncthreads();

        const __half* Kb = Ks[t & 1];
        const half2* Vb = Vp[t & 1];

        // S = Q K^T
        float s[8][4];
#pragma unroll
        for (int nt = 0; nt < 8; nt++)
#pragma unroll
            for (int r = 0; r < 4; r++) s[nt][r] = 0.f;
#pragma unroll
        for (int ks = 0; ks < 4; ks++) {
            int kk = ks * 16;
#pragma unroll
            for (int nt = 0; nt < 8; nt++) {
                const __half* kp = Kb + (nt * 8 + g) * KSTR + kk + 2 * q;
                uint32_t bb[2];
                bb[0] = *(const uint32_t*)kp;
                bb[1] = *(const uint32_t*)(kp + 8);
                mma_f16(s[nt], qf[ks], bb, s[nt]);
            }
        }

        // online softmax
        float mx0 = -1e30f, mx1 = -1e30f;
#pragma unroll
        for (int nt = 0; nt < 8; nt++) {
            mx0 = fmaxf(mx0, fmaxf(s[nt][0], s[nt][1]));
            mx1 = fmaxf(mx1, fmaxf(s[nt][2], s[nt][3]));
        }
        mx0 = fmaxf(mx0, __shfl_xor_sync(0xffffffffu, mx0, 1));
        mx0 = fmaxf(mx0, __shfl_xor_sync(0xffffffffu, mx0, 2));
        mx1 = fmaxf(mx1, __shfl_xor_sync(0xffffffffu, mx1, 1));
        mx1 = fmaxf(mx1, __shfl_xor_sync(0xffffffffu, mx1, 2));

        float nm0 = fmaxf(m0v, mx0), nm1 = fmaxf(m1v, mx1);
        float a0 = __expf(m0v - nm0), a1 = __expf(m1v - nm1);
        m0v = nm0; m1v = nm1;
        l0 *= a0; l1 *= a1;
#pragma unroll
        for (int nt = 0; nt < 8; nt++) {
            o[nt][0] *= a0; o[nt][1] *= a0;
            o[nt][2] *= a1; o[nt][3] *= a1;
        }
        float ps0 = 0.f, ps1 = 0.f;
#pragma unroll
        for (int nt = 0; nt < 8; nt++) {
            s[nt][0] = __expf(s[nt][0] - nm0);
            s[nt][1] = __expf(s[nt][1] - nm0);
            s[nt][2] = __expf(s[nt][2] - nm1);
            s[nt][3] = __expf(s[nt][3] - nm1);
            ps0 += s[nt][0] + s[nt][1];
            ps1 += s[nt][2] + s[nt][3];
        }
        ps0 += __shfl_xor_sync(0xffffffffu, ps0, 1);
        ps0 += __shfl_xor_sync(0xffffffffu, ps0, 2);
        ps1 += __shfl_xor_sync(0xffffffffu, ps1, 1);
        ps1 += __shfl_xor_sync(0xffffffffu, ps1, 2);
        l0 += ps0; l1 += ps1;

        // O += P V   (P A-frags from registers; B frags from packed V)
#pragma unroll
        for (int k2 = 0; k2 < 4; k2++) {
            uint32_t af[4];
            af[0] = h2u(__floats2half2_rn(s[2 * k2][0],     s[2 * k2][1]));
            af[1] = h2u(__floats2half2_rn(s[2 * k2][2],     s[2 * k2][3]));
            af[2] = h2u(__floats2half2_rn(s[2 * k2 + 1][0], s[2 * k2 + 1][1]));
            af[3] = h2u(__floats2half2_rn(s[2 * k2 + 1][2], s[2 * k2 + 1][3]));
#pragma unroll
            for (int nt = 0; nt < 8; nt++) {
                uint32_t bb[2];
                bb[0] = h2u(Vb[(k2 * 8 + q) * VSTR + nt * 8 + g]);
                bb[1] = h2u(Vb[(k2 * 8 + q + 4) * VSTR + nt * 8 + g]);
                mma_f16(o[nt], af, bb, o[nt]);
            }
        }
        __syncthreads();
    }

    float inv0 = 1.f / l0, inv1 = 1.f / l1;
    __half* o0 = outh + (size_t)(b * N_ + qrow) * C_ + h * HD_;
    __half* o1 = o0 + (size_t)8 * C_;
#pragma unroll
    for (int nt = 0; nt < 8; nt++) {
        int c = nt * 8 + 2 * q;
        *(half2*)(o0 + c) = __floats2half2_rn(o[nt][0] * inv0, o[nt][1] * inv0);
        *(half2*)(o1 + c) = __floats2half2_rn(o[nt][2] * inv1, o[nt][3] * inv1);
    }
}

// ============================================================
// Launch orchestration
// ============================================================
extern "C" void kernel_launch(void* const* d_in, const int* in_sizes, int n_in,
                              void* d_out, int out_size) {
    const float* x      = (const float*)d_in[0];
    const float* w_qkv  = (const float*)d_in[1];
    const float* w_proj = (const float*)d_in[2];
    const float* b_proj = (const float*)d_in[3];
    const float* g1     = (const float*)d_in[4];
    const float* beta1  = (const float*)d_in[5];
    const float* g2     = (const float*)d_in[6];
    const float* beta2  = (const float*)d_in[7];
    const float* w_fc1  = (const float*)d_in[8];
    const float* b_fc1  = (const float*)d_in[9];
    const float* w_fc2  = (const float*)d_in[10];
    const float* b_fc2  = (const float*)d_in[11];
    const float* cos_x  = (const float*)d_in[12];
    const float* sin_x  = (const float*)d_in[13];
    const float* cos_y  = (const float*)d_in[14];
    const float* sin_y  = (const float*)d_in[15];
    float* out = (float*)d_out;

    __half *xnh, *qkvh, *attnh, *hh, *wqkvh, *wprojh, *wfc1h, *wfc2h;
    float* x1;
    half2* vt;
    cudaGetSymbolAddress((void**)&xnh,   g_xnh);
    cudaGetSymbolAddress((void**)&qkvh,  g_qkvh);
    cudaGetSymbolAddress((void**)&attnh, g_attnh);
    cudaGetSymbolAddress((void**)&x1,    g_x1);
    cudaGetSymbolAddress((void**)&hh,    g_hh);
    cudaGetSymbolAddress((void**)&vt,    g_vt);
    cudaGetSymbolAddress((void**)&wqkvh, g_wqkvh);
    cudaGetSymbolAddress((void**)&wprojh, g_wprojh);
    cudaGetSymbolAddress((void**)&wfc1h, g_wfc1h);
    cudaGetSymbolAddress((void**)&wfc2h, g_wfc2h);

    cudaFuncSetAttribute(gemm_h<0, 1>, cudaFuncAttributeMaxDynamicSharedMemorySize, SMEM_GEMM);
    cudaFuncSetAttribute(gemm_h<0, 0>, cudaFuncAttributeMaxDynamicSharedMemorySize, SMEM_GEMM);
    cudaFuncSetAttribute(gemm_h<1, 1>, cudaFuncAttributeMaxDynamicSharedMemorySize, SMEM_GEMM);

    // weight conversions
    f2h_kernel<<<(QKVD * C_ / 8 + 255) / 256, 256>>>(w_qkv, wqkvh, QKVD * C_ / 8);
    f2h_kernel<<<(C_ * C_ / 8 + 255) / 256, 256>>>(w_proj, wprojh, C_ * C_ / 8);
    f2h_kernel<<<(4 * C_ * C_ / 8 + 255) / 256, 256>>>(w_fc1, wfc1h, 4 * C_ * C_ / 8);
    f2h_kernel<<<(4 * C_ * C_ / 8 + 255) / 256, 256>>>(w_fc2, wfc2h, 4 * C_ * C_ / 8);

    // 1. LN1 -> half
    ln_h<<<M_, 256>>>(x, g1, beta1, xnh);
    // 2. QKV projection -> half
    gemm_h<0, 1><<<dim3(QKVD / 128, M_ / 128), 256, SMEM_GEMM>>>(
        xnh, wqkvh, nullptr, nullptr, qkvh, M_, QKVD, C_);
    // 3. RoPE in place on q,k
    rope_h<<<(M_ * 2 * H_ * 2 * 16) / 256, 256>>>(qkvh, cos_x, sin_x, cos_y, sin_y);
    // 4. V transpose-pack
    vpack<<<(B_ * H_ * (N_ / 2) * 8) / 256, 256>>>(qkvh, vt);
    // 5. Attention -> half
    attn_h<<<dim3(N_ / 64, B_ * H_), 128>>>(qkvh, vt, attnh);
    // 6. proj + bias + residual(x) -> x1 (fp32)
    gemm_h<0, 0><<<dim3(C_ / 128, M_ / 128), 256, SMEM_GEMM>>>(
        attnh, wprojh, b_proj, x, x1, M_, C_, C_);
    // 7. LN2 -> half
    ln_h<<<M_, 256>>>(x1, g2, beta2, xnh);
    // 8. FC1 + bias + GELU -> half
    gemm_h<1, 1><<<dim3(4 * C_ / 128, M_ / 128), 256, SMEM_GEMM>>>(
        xnh, wfc1h, b_fc1, nullptr, hh, M_, 4 * C_, C_);
    // 9. FC2 + bias + residual(x1) -> out (fp32)
    gemm_h<0, 0><<<dim3(C_ / 128, M_ / 128), 256, SMEM_GEMM>>>(
        hh, wfc2h, b_fc2, x1, out, M_, C_, 4 * C_);
}

// round 4
// speedup vs baseline: 6.5464x; 1.0309x over previous
#include <cuda_runtime.h>
#include <cuda_fp16.h>
#include <cstdint>
#include <cstddef>

constexpr int B_ = 2, N_ = 3072, C_ = 768, H_ = 12, HD_ = 64;
constexpr int M_ = B_ * N_;           // 6144
constexpr int QKVD = 3 * C_;          // 2304

// ---- static scratch ----
__device__ __half g_xnh[M_ * C_];
__device__ __half g_qkvh[(size_t)M_ * QKVD];
__device__ __half g_attnh[M_ * C_];
__device__ float  g_x1[M_ * C_];
__device__ __half g_hh[(size_t)M_ * 4 * C_];
__device__ __half g_wqkvh[QKVD * C_];
__device__ __half g_wprojh[C_ * C_];
__device__ __half g_wfc1h[4 * C_ * C_];
__device__ __half g_wfc2h[C_ * 4 * C_];

// ---- ptx helpers ----
__device__ __forceinline__ void mma_f16(float* d, const uint32_t* a,
                                        const uint32_t* b, const float* c) {
    asm volatile(
        "mma.sync.aligned.m16n8k16.row.col.f32.f16.f16.f32 "
        "{%0,%1,%2,%3},{%4,%5,%6,%7},{%8,%9},{%10,%11,%12,%13};"
        : "=f"(d[0]), "=f"(d[1]), "=f"(d[2]), "=f"(d[3])
        : "r"(a[0]), "r"(a[1]), "r"(a[2]), "r"(a[3]),
          "r"(b[0]), "r"(b[1]),
          "f"(c[0]), "f"(c[1]), "f"(c[2]), "f"(c[3]));
}
__device__ __forceinline__ void ldsm4(uint32_t* r, uint32_t a) {
    asm volatile("ldmatrix.sync.aligned.m8n8.x4.shared.b16 {%0,%1,%2,%3}, [%4];"
                 : "=r"(r[0]), "=r"(r[1]), "=r"(r[2]), "=r"(r[3]) : "r"(a));
}
__device__ __forceinline__ void ldsm4t(uint32_t* r, uint32_t a) {
    asm volatile("ldmatrix.sync.aligned.m8n8.x4.trans.shared.b16 {%0,%1,%2,%3}, [%4];"
                 : "=r"(r[0]), "=r"(r[1]), "=r"(r[2]), "=r"(r[3]) : "r"(a));
}
__device__ __forceinline__ void cpa16(uint32_t dst, const void* src) {
    asm volatile("cp.async.cg.shared.global [%0], [%1], 16;\n" :: "r"(dst), "l"(src));
}
#define CP_COMMIT() asm volatile("cp.async.commit_group;\n" ::: "memory")
#define CP_WAIT1()  asm volatile("cp.async.wait_group 1;\n" ::: "memory")

__device__ __forceinline__ uint32_t h2u(half2 h) { return *(uint32_t*)&h; }

// ============================================================
// fused fp32 -> fp16 conversion for all 4 weight matrices
// ============================================================
constexpr int N8_QKV = QKVD * C_ / 8;        // 221184
constexpr int N8_PRJ = C_ * C_ / 8;          // 73728
constexpr int N8_FC  = 4 * C_ * C_ / 8;      // 294912
constexpr int N8_TOT = N8_QKV + N8_PRJ + 2 * N8_FC;

__global__ void f2h_all(const float* __restrict__ s0, const float* __restrict__ s1,
                        const float* __restrict__ s2, const float* __restrict__ s3,
                        __half* __restrict__ d0, __half* __restrict__ d1,
                        __half* __restrict__ d2, __half* __restrict__ d3) {
    int i = blockIdx.x * blockDim.x + threadIdx.x;
    if (i >= N8_TOT) return;
    const float* s; __half* d;
    if (i < N8_QKV)                       { s = s0; d = d0; }
    else if (i < N8_QKV + N8_PRJ)         { s = s1; d = d1; i -= N8_QKV; }
    else if (i < N8_QKV + N8_PRJ + N8_FC) { s = s2; d = d2; i -= N8_QKV + N8_PRJ; }
    else                                  { s = s3; d = d3; i -= N8_QKV + N8_PRJ + N8_FC; }
    const float4* sp = (const float4*)s;
    float4 a = sp[2 * i], b = sp[2 * i + 1];
    half2 h[4] = {__floats2half2_rn(a.x, a.y), __floats2half2_rn(a.z, a.w),
                  __floats2half2_rn(b.x, b.y), __floats2half2_rn(b.z, b.w)};
    ((uint4*)d)[i] = *(uint4*)h;
}

// ============================================================
// LayerNorm -> half output
// ============================================================
__global__ void ln_h(const float* __restrict__ x, const float* __restrict__ g,
                     const float* __restrict__ b, __half* __restrict__ out) {
    int row = blockIdx.x;
    int tid = threadIdx.x;
    const float* xr = x + (size_t)row * C_;
    float v[3];
    float s = 0.f, sq = 0.f;
#pragma unroll
    for (int i = 0; i < 3; i++) {
        v[i] = xr[tid + i * 256];
        s += v[i];
        sq += v[i] * v[i];
    }
#pragma unroll
    for (int o = 16; o > 0; o >>= 1) {
        s  += __shfl_xor_sync(0xffffffffu, s, o);
        sq += __shfl_xor_sync(0xffffffffu, sq, o);
    }
    __shared__ float ws[8], wq[8];
    int wid = tid >> 5, lid = tid & 31;
    if (lid == 0) { ws[wid] = s; wq[wid] = sq; }
    __syncthreads();
    if (tid == 0) {
        float ts = 0.f, tq = 0.f;
#pragma unroll
        for (int i = 0; i < 8; i++) { ts += ws[i]; tq += wq[i]; }
        float mean = ts * (1.0f / C_);
        float var  = tq * (1.0f / C_) - mean * mean;
        ws[0] = mean;
        wq[0] = rsqrtf(var + 1e-5f);
    }
    __syncthreads();
    float mean = ws[0], rstd = wq[0];
    __half* orow = out + (size_t)row * C_;
#pragma unroll
    for (int i = 0; i < 3; i++) {
        int c = tid + i * 256;
        orow[c] = __float2half_rn((v[i] - mean) * rstd * g[c] + b[c]);
    }
}

// ============================================================
// fp16 tensor-core GEMM NT, ldmatrix for both A and B frags.
// 128x128x32 tiles, 8 warps, 3-stage cp.async.
// ============================================================
constexpr int ASTR = 40;
constexpr int GSTG = 128 * ASTR;
constexpr int SMEM_GEMM = 2 * 3 * GSTG * 2;

template <int ACT, int OUTH>
__global__ void __launch_bounds__(256)
gemm_h(const __half* __restrict__ A, const __half* __restrict__ W,
       const float* __restrict__ bias, const float* __restrict__ resid,
       void* __restrict__ Cout, int M, int Nd, int K)
{
    extern __shared__ __half sm[];
    __half* As = sm;
    __half* Ws = sm + 3 * GSTG;

    const int tid = threadIdx.x, lane = tid & 31, wid = tid >> 5;
    const int warpM = wid >> 2, warpN = wid & 3;
    const int g = lane >> 2, q = lane & 3;
    const int m0 = blockIdx.y * 128, n0 = blockIdx.x * 128;

    const uint32_t asbase = (uint32_t)__cvta_generic_to_shared(As);
    const uint32_t wsbase = (uint32_t)__cvta_generic_to_shared(Ws);

    const int ar0 = tid >> 2,           ac0 = (tid & 3) * 8;
    const int ar1 = (tid + 256) >> 2,   ac1 = ((tid + 256) & 3) * 8;

    auto stage = [&](int t, int s) {
        int k0 = t * 32;
        uint32_t ab = asbase + s * (GSTG * 2);
        uint32_t wb = wsbase + s * (GSTG * 2);
        cpa16(ab + (ar0 * ASTR + ac0) * 2, A + (size_t)(m0 + ar0) * K + k0 + ac0);
        cpa16(ab + (ar1 * ASTR + ac1) * 2, A + (size_t)(m0 + ar1) * K + k0 + ac1);
        cpa16(wb + (ar0 * ASTR + ac0) * 2, W + (size_t)(n0 + ar0) * K + k0 + ac0);
        cpa16(wb + (ar1 * ASTR + ac1) * 2, W + (size_t)(n0 + ar1) * K + k0 + ac1);
    };

    float acc[4][4][4];
#pragma unroll
    for (int mt = 0; mt < 4; mt++)
#pragma unroll
        for (int nt = 0; nt < 4; nt++)
#pragma unroll
            for (int r = 0; r < 4; r++) acc[mt][nt][r] = 0.f;

    const int T = K / 32;
    stage(0, 0); CP_COMMIT();
    stage(1, 1); CP_COMMIT();

    // A frag ldsm pattern (16x16 per mt)
    const int lrow = warpM * 64 + (lane & 7) + ((lane >> 3) & 1) * 8;
    const int lcol = (lane >> 4) * 8;
    // B frag ldsm pattern (16 n-rows x 16 k-cols per nt-pair)
    const int brow = (lane & 7) + ((lane >> 4) & 1) * 8;
    const int bcol = ((lane >> 3) & 1) * 8;

    for (int t = 0; t < T; t++) {
        CP_WAIT1();
        __syncthreads();
        if (t + 2 < T) stage(t + 2, (t + 2) % 3);
        CP_COMMIT();
        const int s = t % 3;
        const uint32_t ab = asbase + s * (GSTG * 2);
        const uint32_t wb = wsbase + s * (GSTG * 2);
#pragma unroll
        for (int kk = 0; kk < 32; kk += 16) {
            uint32_t af[4][4];
#pragma unroll
            for (int mt = 0; mt < 4; mt++)
                ldsm4(af[mt], ab + ((lrow + mt * 16) * ASTR + lcol + kk) * 2);
            uint32_t bf[4][2];
#pragma unroll
            for (int ntp = 0; ntp < 2; ntp++) {
                uint32_t r[4];
                ldsm4(r, wb + ((warpN * 32 + ntp * 16 + brow) * ASTR + kk + bcol) * 2);
                bf[2 * ntp][0] = r[0]; bf[2 * ntp][1] = r[1];
                bf[2 * ntp + 1][0] = r[2]; bf[2 * ntp + 1][1] = r[3];
            }
#pragma unroll
            for (int mt = 0; mt < 4; mt++)
#pragma unroll
                for (int nt = 0; nt < 4; nt++)
                    mma_f16(acc[mt][nt], af[mt], bf[nt], acc[mt][nt]);
        }
    }

    // epilogue
#pragma unroll
    for (int mt = 0; mt < 4; mt++) {
#pragma unroll
        for (int nt = 0; nt < 4; nt++) {
            int m = m0 + warpM * 64 + mt * 16 + g;
            int c = n0 + warpN * 32 + nt * 8 + 2 * q;
            float bv0 = bias ? bias[c] : 0.f;
            float bv1 = bias ? bias[c + 1] : 0.f;
            float v0 = acc[mt][nt][0] + bv0, v1 = acc[mt][nt][1] + bv1;
            float v2 = acc[mt][nt][2] + bv0, v3 = acc[mt][nt][3] + bv1;
            if (ACT == 1) {
                v0 = 0.5f * v0 * (1.0f + erff(v0 * 0.70710678118654752f));
                v1 = 0.5f * v1 * (1.0f + erff(v1 * 0.70710678118654752f));
                v2 = 0.5f * v2 * (1.0f + erff(v2 * 0.70710678118654752f));
                v3 = 0.5f * v3 * (1.0f + erff(v3 * 0.70710678118654752f));
            }
            size_t i0 = (size_t)m * Nd + c, i1 = (size_t)(m + 8) * Nd + c;
            if (OUTH) {
                __half* O = (__half*)Cout;
                *(half2*)(O + i0) = __floats2half2_rn(v0, v1);
                *(half2*)(O + i1) = __floats2half2_rn(v2, v3);
            } else {
                float* O = (float*)Cout;
                if (resid) {
                    float2 r0 = *(const float2*)&resid[i0];
                    float2 r1 = *(const float2*)&resid[i1];
                    v0 += r0.x; v1 += r0.y; v2 += r1.x; v3 += r1.y;
                }
                *(float2*)&O[i0] = make_float2(v0, v1);
                *(float2*)&O[i1] = make_float2(v2, v3);
            }
        }
    }
}

// ============================================================
// 2D RoPE in place on half qkv (q and k sections)
// ============================================================
__global__ void rope_h(__half* __restrict__ qkv,
                       const float* __restrict__ cx, const float* __restrict__ sx,
                       const float* __restrict__ cy, const float* __restrict__ sy)
{
    int t = blockIdx.x * blockDim.x + threadIdx.x;
    int j = t & 15;  t >>= 4;
    int half_ = t & 1; t >>= 1;
    int h = t % 12;   t /= 12;
    int which = t & 1;
    int tok = t >> 1;
    if (tok >= M_) return;
    int n = tok % N_;

    __half* p = qkv + (size_t)tok * QKVD + which * C_ + h * HD_ + half_ * 32;
    const float* ct = half_ ? cx : cy;
    const float* st = half_ ? sx : sy;
    float t1 = __half2float(p[j]), t2 = __half2float(p[j + 16]);
    float c1 = ct[n * 32 + j],      s1 = st[n * 32 + j];
    float c2 = ct[n * 32 + j + 16], s2 = st[n * 32 + j + 16];
    p[j]      = __float2half_rn(t1 * c1 - t2 * s1);
    p[j + 16] = __float2half_rn(t2 * c2 + t1 * s2);
}

// ============================================================
// Flash attention fp16 mma, 128 q-rows per block (8 warps),
// double-buffered cp.async K/V tiles, ldmatrix fragments.
// ============================================================
constexpr int KSTR = 72;   // halves per smem row -> conflict-free ldsm

__global__ void __launch_bounds__(256)
attn_h(const __half* __restrict__ qkvh, __half* __restrict__ outh)
{
    __shared__ __half Ks[2][64 * KSTR];
    __shared__ __half Vs[2][64 * KSTR];

    const int tid = threadIdx.x, lane = tid & 31, wid = tid >> 5;
    const int g = lane >> 2, q = lane & 3;
    const int bh = blockIdx.y, b = bh / H_, h = bh % H_;
    const int qrow = blockIdx.x * 128 + wid * 16 + g;

    const uint32_t ksbase = (uint32_t)__cvta_generic_to_shared(&Ks[0][0]);
    const uint32_t vsbase = (uint32_t)__cvta_generic_to_shared(&Vs[0][0]);

    // ldsm lane patterns
    const int brow = (lane & 7) + ((lane >> 4) & 1) * 8;  // non-trans B (QK)
    const int bcol = ((lane >> 3) & 1) * 8;
    const int vrow = (lane & 7) + ((lane >> 3) & 1) * 8;  // trans B (PV)
    const int vcol = ((lane >> 4) & 1) * 8;

    // Q fragments (x 0.125 exact in fp16)
    uint32_t qf[4][4];
    {
        const __half* q0 = qkvh + (size_t)(b * N_ + qrow) * QKVD + h * HD_;
        const __half* q1 = q0 + (size_t)8 * QKVD;
        const half2 sc = __float2half2_rn(0.125f);
#pragma unroll
        for (int ks = 0; ks < 4; ks++) {
            int col = ks * 16 + 2 * q;
            qf[ks][0] = h2u(__hmul2(*(const half2*)(q0 + col), sc));
            qf[ks][1] = h2u(__hmul2(*(const half2*)(q1 + col), sc));
            qf[ks][2] = h2u(__hmul2(*(const half2*)(q0 + col + 8), sc));
            qf[ks][3] = h2u(__hmul2(*(const half2*)(q1 + col + 8), sc));
        }
    }

    const size_t kgbase = (size_t)(b * N_) * QKVD + C_ + h * HD_;
    const size_t vgbase = kgbase + C_;

    auto stage = [&](int kt, int buf) {
#pragma unroll
        for (int i = 0; i < 2; i++) {
            int idx = tid + i * 256;           // 0..511
            int r = idx >> 3, c = idx & 7;
            size_t roff = (size_t)(kt + r) * QKVD + c * 8;
            cpa16(ksbase + (buf * 64 * KSTR + r * KSTR + c * 8) * 2, qkvh + kgbase + roff);
            cpa16(vsbase + (buf * 64 * KSTR + r * KSTR + c * 8) * 2, qkvh + vgbase + roff);
        }
    };

    float o[8][4];
#pragma unroll
    for (int nt = 0; nt < 8; nt++)
#pragma unroll
        for (int r = 0; r < 4; r++) o[nt][r] = 0.f;
    float m0v = -1e30f, m1v = -1e30f, l0 = 0.f, l1 = 0.f;

    stage(0, 0); CP_COMMIT();

    constexpr int T = N_ / 64;   // 48
    for (int t = 0; t < T; t++) {
        if (t + 1 < T) stage((t + 1) * 64, (t + 1) & 1);
        CP_COMMIT();
        CP_WAIT1();
        __syncthreads();

        const uint32_t kb = ksbase + (t & 1) * (64 * KSTR * 2);
        const uint32_t vb = vsbase + (t & 1) * (64 * KSTR * 2);

        // S = Q K^T
        float s[8][4];
#pragma unroll
        for (int nt = 0; nt < 8; nt++)
#pragma unroll
            for (int r = 0; r < 4; r++) s[nt][r] = 0.f;
#pragma unroll
        for (int ks = 0; ks < 4; ks++) {
#pragma unroll
            for (int ntp = 0; ntp < 4; ntp++) {
                uint32_t r[4];
                ldsm4(r, kb + ((ntp * 16 + brow) * KSTR + ks * 16 + bcol) * 2);
                mma_f16(s[2 * ntp],     qf[ks], r,     s[2 * ntp]);
                mma_f16(s[2 * ntp + 1], qf[ks], r + 2, s[2 * ntp + 1]);
            }
        }

        // online softmax
        float mx0 = -1e30f, mx1 = -1e30f;
#pragma unroll
        for (int nt = 0; nt < 8; nt++) {
            mx0 = fmaxf(mx0, fmaxf(s[nt][0], s[nt][1]));
            mx1 = fmaxf(mx1, fmaxf(s[nt][2], s[nt][3]));
        }
        mx0 = fmaxf(mx0, __shfl_xor_sync(0xffffffffu, mx0, 1));
        mx0 = fmaxf(mx0, __shfl_xor_sync(0xffffffffu, mx0, 2));
        mx1 = fmaxf(mx1, __shfl_xor_sync(0xffffffffu, mx1, 1));
        mx1 = fmaxf(mx1, __shfl_xor_sync(0xffffffffu, mx1, 2));

        float nm0 = fmaxf(m0v, mx0), nm1 = fmaxf(m1v, mx1);
        float a0 = __expf(m0v - nm0), a1 = __expf(m1v - nm1);
        m0v = nm0; m1v = nm1;
        l0 *= a0; l1 *= a1;
#pragma unroll
        for (int nt = 0; nt < 8; nt++) {
            o[nt][0] *= a0; o[nt][1] *= a0;
            o[nt][2] *= a1; o[nt][3] *= a1;
        }
        float ps0 = 0.f, ps1 = 0.f;
#pragma unroll
        for (int nt = 0; nt < 8; nt++) {
            s[nt][0] = __expf(s[nt][0] - nm0);
            s[nt][1] = __expf(s[nt][1] - nm0);
            s[nt][2] = __expf(s[nt][2] - nm1);
            s[nt][3] = __expf(s[nt][3] - nm1);
            ps0 += s[nt][0] + s[nt][1];
            ps1 += s[nt][2] + s[nt][3];
        }
        ps0 += __shfl_xor_sync(0xffffffffu, ps0, 1);
        ps0 += __shfl_xor_sync(0xffffffffu, ps0, 2);
        ps1 += __shfl_xor_sync(0xffffffffu, ps1, 1);
        ps1 += __shfl_xor_sync(0xffffffffu, ps1, 2);
        l0 += ps0; l1 += ps1;

        // O += P V  (A frags repacked from s; B frags via trans ldsm on V)
#pragma unroll
        for (int k2 = 0; k2 < 4; k2++) {
            uint32_t af[4];
            af[0] = h2u(__floats2half2_rn(s[2 * k2][0],     s[2 * k2][1]));
            af[1] = h2u(__floats2half2_rn(s[2 * k2][2],     s[2 * k2][3]));
            af[2] = h2u(__floats2half2_rn(s[2 * k2 + 1][0], s[2 * k2 + 1][1]));
            af[3] = h2u(__floats2half2_rn(s[2 * k2 + 1][2], s[2 * k2 + 1][3]));
#pragma unroll
            for (int ntp = 0; ntp < 4; ntp++) {
                uint32_t r[4];
                ldsm4t(r, vb + ((k2 * 16 + vrow) * KSTR + ntp * 16 + vcol) * 2);
                mma_f16(o[2 * ntp],     af, r,     o[2 * ntp]);
                mma_f16(o[2 * ntp + 1], af, r + 2, o[2 * ntp + 1]);
            }
        }
        __syncthreads();
    }

    float inv0 = 1.f / l0, inv1 = 1.f / l1;
    __half* o0 = outh + (size_t)(b * N_ + qrow) * C_ + h * HD_;
    __half* o1 = o0 + (size_t)8 * C_;
#pragma unroll
    for (int nt = 0; nt < 8; nt++) {
        int c = nt * 8 + 2 * q;
        *(half2*)(o0 + c) = __floats2half2_rn(o[nt][0] * inv0, o[nt][1] * inv0);
        *(half2*)(o1 + c) = __floats2half2_rn(o[nt][2] * inv1, o[nt][3] * inv1);
    }
}

// ============================================================
// Launch orchestration
// ============================================================
extern "C" void kernel_launch(void* const* d_in, const int* in_sizes, int n_in,
                              void* d_out, int out_size) {
    const float* x      = (const float*)d_in[0];
    const float* w_qkv  = (const float*)d_in[1];
    const float* w_proj = (const float*)d_in[2];
    const float* b_proj = (const float*)d_in[3];
    const float* g1     = (const float*)d_in[4];
    const float* beta1  = (const float*)d_in[5];
    const float* g2     = (const float*)d_in[6];
    const float* beta2  = (const float*)d_in[7];
    const float* w_fc1  = (const float*)d_in[8];
    const float* b_fc1  = (const float*)d_in[9];
    const float* w_fc2  = (const float*)d_in[10];
    const float* b_fc2  = (const float*)d_in[11];
    const float* cos_x  = (const float*)d_in[12];
    const float* sin_x  = (const float*)d_in[13];
    const float* cos_y  = (const float*)d_in[14];
    const float* sin_y  = (const float*)d_in[15];
    float* out = (float*)d_out;

    __half *xnh, *qkvh, *attnh, *hh, *wqkvh, *wprojh, *wfc1h, *wfc2h;
    float* x1;
    cudaGetSymbolAddress((void**)&xnh,   g_xnh);
    cudaGetSymbolAddress((void**)&qkvh,  g_qkvh);
    cudaGetSymbolAddress((void**)&attnh, g_attnh);
    cudaGetSymbolAddress((void**)&x1,    g_x1);
    cudaGetSymbolAddress((void**)&hh,    g_hh);
    cudaGetSymbolAddress((void**)&wqkvh, g_wqkvh);
    cudaGetSymbolAddress((void**)&wprojh, g_wprojh);
    cudaGetSymbolAddress((void**)&wfc1h, g_wfc1h);
    cudaGetSymbolAddress((void**)&wfc2h, g_wfc2h);

    cudaFuncSetAttribute(gemm_h<0, 1>, cudaFuncAttributeMaxDynamicSharedMemorySize, SMEM_GEMM);
    cudaFuncSetAttribute(gemm_h<0, 0>, cudaFuncAttributeMaxDynamicSharedMemorySize, SMEM_GEMM);
    cudaFuncSetAttribute(gemm_h<1, 1>, cudaFuncAttributeMaxDynamicSharedMemorySize, SMEM_GEMM);

    // weight conversions (single launch)
    f2h_all<<<(N8_TOT + 255) / 256, 256>>>(w_qkv, w_proj, w_fc1, w_fc2,
                                           wqkvh, wprojh, wfc1h, wfc2h);

    // 1. LN1 -> half
    ln_h<<<M_, 256>>>(x, g1, beta1, xnh);
    // 2. QKV projection -> half
    gemm_h<0, 1><<<dim3(QKVD / 128, M_ / 128), 256, SMEM_GEMM>>>(
        xnh, wqkvh, nullptr, nullptr, qkvh, M_, QKVD, C_);
    // 3. RoPE in place on q,k
    rope_h<<<(M_ * 2 * H_ * 2 * 16) / 256, 256>>>(qkvh, cos_x, sin_x, cos_y, sin_y);
    // 4. Attention -> half
    attn_h<<<dim3(N_ / 128, B_ * H_), 256>>>(qkvh, attnh);
    // 5. proj + bias + residual(x) -> x1 (fp32)
    gemm_h<0, 0><<<dim3(C_ / 128, M_ / 128), 256, SMEM_GEMM>>>(
        attnh, wprojh, b_proj, x, x1, M_, C_, C_);
    // 6. LN2 -> half
    ln_h<<<M_, 256>>>(x1, g2, beta2, xnh);
    // 7. FC1 + bias + GELU -> half
    gemm_h<1, 1><<<dim3(4 * C_ / 128, M_ / 128), 256, SMEM_GEMM>>>(
        xnh, wfc1h, b_fc1, nullptr, hh, M_, 4 * C_, C_);
    // 8. FC2 + bias + residual(x1) -> out (fp32)
    gemm_h<0, 0><<<dim3(C_ / 128, M_ / 128), 256, SMEM_GEMM>>>(
        hh, wfc2h, b_fc2, x1, out, M_, C_, 4 * C_);
}

// round 5
// speedup vs baseline: 6.5926x; 1.0071x over previous
#include <cuda_runtime.h>
#include <cuda_fp16.h>
#include <cstdint>
#include <cstddef>

constexpr int B_ = 2, N_ = 3072, C_ = 768, H_ = 12, HD_ = 64;
constexpr int M_ = B_ * N_;           // 6144
constexpr int QKVD = 3 * C_;          // 2304

// ---- static scratch ----
__device__ __half g_xnh[M_ * C_];
__device__ __half g_qkvh[(size_t)M_ * QKVD];
__device__ __half g_attnh[M_ * C_];
__device__ float  g_x1[M_ * C_];
__device__ __half g_hh[(size_t)M_ * 4 * C_];
__device__ __half g_wqkvh[QKVD * C_];
__device__ __half g_wprojh[C_ * C_];
__device__ __half g_wfc1h[4 * C_ * C_];
__device__ __half g_wfc2h[C_ * 4 * C_];

// ---- ptx helpers ----
__device__ __forceinline__ void mma_f16(float* d, const uint32_t* a,
                                        const uint32_t* b, const float* c) {
    asm volatile(
        "mma.sync.aligned.m16n8k16.row.col.f32.f16.f16.f32 "
        "{%0,%1,%2,%3},{%4,%5,%6,%7},{%8,%9},{%10,%11,%12,%13};"
        : "=f"(d[0]), "=f"(d[1]), "=f"(d[2]), "=f"(d[3])
        : "r"(a[0]), "r"(a[1]), "r"(a[2]), "r"(a[3]),
          "r"(b[0]), "r"(b[1]),
          "f"(c[0]), "f"(c[1]), "f"(c[2]), "f"(c[3]));
}
__device__ __forceinline__ void ldsm4(uint32_t* r, uint32_t a) {
    asm volatile("ldmatrix.sync.aligned.m8n8.x4.shared.b16 {%0,%1,%2,%3}, [%4];"
                 : "=r"(r[0]), "=r"(r[1]), "=r"(r[2]), "=r"(r[3]) : "r"(a));
}
__device__ __forceinline__ void ldsm4t(uint32_t* r, uint32_t a) {
    asm volatile("ldmatrix.sync.aligned.m8n8.x4.trans.shared.b16 {%0,%1,%2,%3}, [%4];"
                 : "=r"(r[0]), "=r"(r[1]), "=r"(r[2]), "=r"(r[3]) : "r"(a));
}
__device__ __forceinline__ void cpa16(uint32_t dst, const void* src) {
    asm volatile("cp.async.cg.shared.global [%0], [%1], 16;\n" :: "r"(dst), "l"(src));
}
#define CP_COMMIT() asm volatile("cp.async.commit_group;\n" ::: "memory")
#define CP_WAIT1()  asm volatile("cp.async.wait_group 1;\n" ::: "memory")

__device__ __forceinline__ uint32_t h2u(half2 h) { return *(uint32_t*)&h; }

// ============================================================
// fused fp32 -> fp16 conversion for all 4 weight matrices
// ============================================================
constexpr int N8_QKV = QKVD * C_ / 8;
constexpr int N8_PRJ = C_ * C_ / 8;
constexpr int N8_FC  = 4 * C_ * C_ / 8;
constexpr int N8_TOT = N8_QKV + N8_PRJ + 2 * N8_FC;

__global__ void f2h_all(const float* __restrict__ s0, const float* __restrict__ s1,
                        const float* __restrict__ s2, const float* __restrict__ s3,
                        __half* __restrict__ d0, __half* __restrict__ d1,
                        __half* __restrict__ d2, __half* __restrict__ d3) {
    int i = blockIdx.x * blockDim.x + threadIdx.x;
    if (i >= N8_TOT) return;
    const float* s; __half* d;
    if (i < N8_QKV)                       { s = s0; d = d0; }
    else if (i < N8_QKV + N8_PRJ)         { s = s1; d = d1; i -= N8_QKV; }
    else if (i < N8_QKV + N8_PRJ + N8_FC) { s = s2; d = d2; i -= N8_QKV + N8_PRJ; }
    else                                  { s = s3; d = d3; i -= N8_QKV + N8_PRJ + N8_FC; }
    const float4* sp = (const float4*)s;
    float4 a = sp[2 * i], b = sp[2 * i + 1];
    half2 h[4] = {__floats2half2_rn(a.x, a.y), __floats2half2_rn(a.z, a.w),
                  __floats2half2_rn(b.x, b.y), __floats2half2_rn(b.z, b.w)};
    ((uint4*)d)[i] = *(uint4*)h;
}

// ============================================================
// LayerNorm -> half output
// ============================================================
__global__ void ln_h(const float* __restrict__ x, const float* __restrict__ g,
                     const float* __restrict__ b, __half* __restrict__ out) {
    int row = blockIdx.x;
    int tid = threadIdx.x;
    const float* xr = x + (size_t)row * C_;
    float v[3];
    float s = 0.f, sq = 0.f;
#pragma unroll
    for (int i = 0; i < 3; i++) {
        v[i] = xr[tid + i * 256];
        s += v[i];
        sq += v[i] * v[i];
    }
#pragma unroll
    for (int o = 16; o > 0; o >>= 1) {
        s  += __shfl_xor_sync(0xffffffffu, s, o);
        sq += __shfl_xor_sync(0xffffffffu, sq, o);
    }
    __shared__ float ws[8], wq[8];
    int wid = tid >> 5, lid = tid & 31;
    if (lid == 0) { ws[wid] = s; wq[wid] = sq; }
    __syncthreads();
    if (tid == 0) {
        float ts = 0.f, tq = 0.f;
#pragma unroll
        for (int i = 0; i < 8; i++) { ts += ws[i]; tq += wq[i]; }
        float mean = ts * (1.0f / C_);
        float var  = tq * (1.0f / C_) - mean * mean;
        ws[0] = mean;
        wq[0] = rsqrtf(var + 1e-5f);
    }
    __syncthreads();
    float mean = ws[0], rstd = wq[0];
    __half* orow = out + (size_t)row * C_;
#pragma unroll
    for (int i = 0; i < 3; i++) {
        int c = tid + i * 256;
        orow[c] = __float2half_rn((v[i] - mean) * rstd * g[c] + b[c]);
    }
}

// ============================================================
// fp16 tensor-core GEMM NT: 128x256x32 block tile, 8 warps (2x4),
// warp tile 64x64, 3-stage cp.async, ldmatrix A+B.
// ROPE=1: fused 2D rope on q/k sections of QKV output (OUTH=1 path).
// ============================================================
constexpr int ASTR = 40;
constexpr int A_STG = 128 * ASTR;          // halves
constexpr int W_STG = 256 * ASTR;
constexpr int SMEM_GEMM = 3 * (A_STG + W_STG) * 2;   // 92160 bytes

template <int ACT, int OUTH, int ROPE>
__global__ void __launch_bounds__(256, 1)
gemm_h(const __half* __restrict__ A, const __half* __restrict__ W,
       const float* __restrict__ bias, const float* __restrict__ resid,
       void* __restrict__ Cout, int M, int Nd, int K,
       const float* __restrict__ cx, const float* __restrict__ sx,
       const float* __restrict__ cy, const float* __restrict__ sy)
{
    extern __shared__ __half sm[];
    __half* As = sm;                    // 3 stages of 128x32 (stride 40)
    __half* Ws = sm + 3 * A_STG;        // 3 stages of 256x32 (stride 40)

    const int tid = threadIdx.x, lane = tid & 31, wid = tid >> 5;
    const int warpM = wid >> 2, warpN = wid & 3;
    const int g = lane >> 2, q = lane & 3;
    const int m0 = blockIdx.y * 128, n0 = blockIdx.x * 256;

    const uint32_t asbase = (uint32_t)__cvta_generic_to_shared(As);
    const uint32_t wsbase = (uint32_t)__cvta_generic_to_shared(Ws);

    const int ar = tid >> 2, ac = (tid & 3) * 8;   // A: 2 slots (rows ar, ar+64)

    auto stage = [&](int t, int s) {
        int k0 = t * 32;
        uint32_t ab = asbase + s * (A_STG * 2);
        uint32_t wb = wsbase + s * (W_STG * 2);
        cpa16(ab + (ar * ASTR + ac) * 2,        A + (size_t)(m0 + ar) * K + k0 + ac);
        cpa16(ab + ((ar + 64) * ASTR + ac) * 2, A + (size_t)(m0 + ar + 64) * K + k0 + ac);
#pragma unroll
        for (int i = 0; i < 4; i++) {
            int r = ar + i * 64;
            cpa16(wb + (r * ASTR + ac) * 2, W + (size_t)(n0 + r) * K + k0 + ac);
        }
    };

    float acc[4][8][4];
#pragma unroll
    for (int mt = 0; mt < 4; mt++)
#pragma unroll
        for (int nt = 0; nt < 8; nt++)
#pragma unroll
            for (int r = 0; r < 4; r++) acc[mt][nt][r] = 0.f;

    const int T = K / 32;
    stage(0, 0); CP_COMMIT();
    stage(1, 1); CP_COMMIT();

    const int lrow = warpM * 64 + (lane & 7) + ((lane >> 3) & 1) * 8;
    const int lcol = (lane >> 4) * 8;
    const int brow = (lane & 7) + ((lane >> 4) & 1) * 8;
    const int bcol = ((lane >> 3) & 1) * 8;

    for (int t = 0; t < T; t++) {
        CP_WAIT1();
        __syncthreads();
        if (t + 2 < T) stage(t + 2, (t + 2) % 3);
        CP_COMMIT();
        const int s = t % 3;
        const uint32_t ab = asbase + s * (A_STG * 2);
        const uint32_t wb = wsbase + s * (W_STG * 2);
#pragma unroll
        for (int kk = 0; kk < 32; kk += 16) {
            uint32_t af[4][4];
#pragma unroll
            for (int mt = 0; mt < 4; mt++)
                ldsm4(af[mt], ab + ((lrow + mt * 16) * ASTR + lcol + kk) * 2);
            uint32_t bf[8][2];
#pragma unroll
            for (int ntp = 0; ntp < 4; ntp++) {
                uint32_t r[4];
                ldsm4(r, wb + ((warpN * 64 + ntp * 16 + brow) * ASTR + kk + bcol) * 2);
                bf[2 * ntp][0] = r[0]; bf[2 * ntp][1] = r[1];
                bf[2 * ntp + 1][0] = r[2]; bf[2 * ntp + 1][1] = r[3];
            }
#pragma unroll
            for (int mt = 0; mt < 4; mt++)
#pragma unroll
                for (int nt = 0; nt < 8; nt++)
                    mma_f16(acc[mt][nt], af[mt], bf[nt], acc[mt][nt]);
        }
    }

    if (ROPE) {
        // QKV output: apply 2D rope to q/k sections in registers, store half.
        __half* O = (__half*)Cout;
        const int chunk = n0 + warpN * 64;          // 64-aligned = one head
        const bool qk = chunk < 2 * C_;             // q or k section
#pragma unroll
        for (int mt = 0; mt < 4; mt++) {
            int m = m0 + warpM * 64 + mt * 16 + g;
            int ntok = m % N_;                      // token for row m; row m+8 -> ntok+8
            if (qk) {
#pragma unroll
                for (int base = 0; base < 8; base += 4) {   // y half then x half
                    const float* ct = base ? cx : cy;
                    const float* st = base ? sx : sy;
#pragma unroll
                    for (int p = 0; p < 2; p++) {
                        int j = p * 8 + 2 * q;              // within-half col of regs 0/1
                        float2 c0 = *(const float2*)&ct[ntok * 32 + j];
                        float2 s0 = *(const float2*)&st[ntok * 32 + j];
                        float2 c1 = *(const float2*)&ct[(ntok + 8) * 32 + j];
                        float2 s1 = *(const float2*)&st[(ntok + 8) * 32 + j];
                        float* lo = acc[mt][base + p];
                        float* hi = acc[mt][base + p + 2];
                        float t1, t2;
                        t1 = lo[0]; t2 = hi[0];
                        lo[0] = t1 * c0.x - t2 * s0.x; hi[0] = t2 * c0.x + t1 * s0.x;
                        t1 = lo[1]; t2 = hi[1];
                        lo[1] = t1 * c0.y - t2 * s0.y; hi[1] = t2 * c0.y + t1 * s0.y;
                        t1 = lo[2]; t2 = hi[2];
                        lo[2] = t1 * c1.x - t2 * s1.x; hi[2] = t2 * c1.x + t1 * s1.x;
                        t1 = lo[3]; t2 = hi[3];
                        lo[3] = t1 * c1.y - t2 * s1.y; hi[3] = t2 * c1.y + t1 * s1.y;
                    }
                }
            }
#pragma unroll
            for (int nt = 0; nt < 8; nt++) {
                int c = chunk + nt * 8 + 2 * q;
                size_t i0 = (size_t)m * Nd + c, i1 = (size_t)(m + 8) * Nd + c;
                *(half2*)(O + i0) = __floats2half2_rn(acc[mt][nt][0], acc[mt][nt][1]);
                *(half2*)(O + i1) = __floats2half2_rn(acc[mt][nt][2], acc[mt][nt][3]);
            }
        }
        return;
    }

    // generic epilogue
#pragma unroll
    for (int mt = 0; mt < 4; mt++) {
#pragma unroll
        for (int nt = 0; nt < 8; nt++) {
            int m = m0 + warpM * 64 + mt * 16 + g;
            int c = n0 + warpN * 64 + nt * 8 + 2 * q;
            float bv0 = bias ? bias[c] : 0.f;
            float bv1 = bias ? bias[c + 1] : 0.f;
            float v0 = acc[mt][nt][0] + bv0, v1 = acc[mt][nt][1] + bv1;
            float v2 = acc[mt][nt][2] + bv0, v3 = acc[mt][nt][3] + bv1;
            if (ACT == 1) {
                v0 = 0.5f * v0 * (1.0f + erff(v0 * 0.70710678118654752f));
                v1 = 0.5f * v1 * (1.0f + erff(v1 * 0.70710678118654752f));
                v2 = 0.5f * v2 * (1.0f + erff(v2 * 0.70710678118654752f));
                v3 = 0.5f * v3 * (1.0f + erff(v3 * 0.70710678118654752f));
            }
            size_t i0 = (size_t)m * Nd + c, i1 = (size_t)(m + 8) * Nd + c;
            if (OUTH) {
                __half* O = (__half*)Cout;
                *(half2*)(O + i0) = __floats2half2_rn(v0, v1);
                *(half2*)(O + i1) = __floats2half2_rn(v2, v3);
            } else {
                float* O = (float*)Cout;
                if (resid) {
                    float2 r0 = *(const float2*)&resid[i0];
                    float2 r1 = *(const float2*)&resid[i1];
                    v0 += r0.x; v1 += r0.y; v2 += r1.x; v3 += r1.y;
                }
                *(float2*)&O[i0] = make_float2(v0, v1);
                *(float2*)&O[i1] = make_float2(v2, v3);
            }
        }
    }
}

// ============================================================
// Flash attention fp16 mma, 128 q-rows per block (8 warps),
// double-buffered cp.async K/V tiles, ldmatrix fragments.
// ============================================================
constexpr int KSTR = 72;

__global__ void __launch_bounds__(256)
attn_h(const __half* __restrict__ qkvh, __half* __restrict__ outh)
{
    __shared__ __half Ks[2][64 * KSTR];
    __shared__ __half Vs[2][64 * KSTR];

    const int tid = threadIdx.x, lane = tid & 31, wid = tid >> 5;
    const int g = lane >> 2, q = lane & 3;
    const int bh = blockIdx.y, b = bh / H_, h = bh % H_;
    const int qrow = blockIdx.x * 128 + wid * 16 + g;

    const uint32_t ksbase = (uint32_t)__cvta_generic_to_shared(&Ks[0][0]);
    const uint32_t vsbase = (uint32_t)__cvta_generic_to_shared(&Vs[0][0]);

    const int brow = (lane & 7) + ((lane >> 4) & 1) * 8;
    const int bcol = ((lane >> 3) & 1) * 8;
    const int vrow = (lane & 7) + ((lane >> 3) & 1) * 8;
    const int vcol = ((lane >> 4) & 1) * 8;

    uint32_t qf[4][4];
    {
        const __half* q0 = qkvh + (size_t)(b * N_ + qrow) * QKVD + h * HD_;
        const __half* q1 = q0 + (size_t)8 * QKVD;
        const half2 sc = __float2half2_rn(0.125f);
#pragma unroll
        for (int ks = 0; ks < 4; ks++) {
            int col = ks * 16 + 2 * q;
            qf[ks][0] = h2u(__hmul2(*(const half2*)(q0 + col), sc));
            qf[ks][1] = h2u(__hmul2(*(const half2*)(q1 + col), sc));
            qf[ks][2] = h2u(__hmul2(*(const half2*)(q0 + col + 8), sc));
            qf[ks][3] = h2u(__hmul2(*(const half2*)(q1 + col + 8), sc));
        }
    }

    const size_t kgbase = (size_t)(b * N_) * QKVD + C_ + h * HD_;
    const size_t vgbase = kgbase + C_;

    auto stage = [&](int kt, int buf) {
#pragma unroll
        for (int i = 0; i < 2; i++) {
            int idx = tid + i * 256;
            int r = idx >> 3, c = idx & 7;
            size_t roff = (size_t)(kt + r) * QKVD + c * 8;
            cpa16(ksbase + (buf * 64 * KSTR + r * KSTR + c * 8) * 2, qkvh + kgbase + roff);
            cpa16(vsbase + (buf * 64 * KSTR + r * KSTR + c * 8) * 2, qkvh + vgbase + roff);
        }
    };

    float o[8][4];
#pragma unroll
    for (int nt = 0; nt < 8; nt++)
#pragma unroll
        for (int r = 0; r < 4; r++) o[nt][r] = 0.f;
    float m0v = -1e30f, m1v = -1e30f, l0 = 0.f, l1 = 0.f;

    stage(0, 0); CP_COMMIT();

    constexpr int T = N_ / 64;
    for (int t = 0; t < T; t++) {
        if (t + 1 < T) stage((t + 1) * 64, (t + 1) & 1);
        CP_COMMIT();
        CP_WAIT1();
        __syncthreads();

        const uint32_t kb = ksbase + (t & 1) * (64 * KSTR * 2);
        const uint32_t vb = vsbase + (t & 1) * (64 * KSTR * 2);

        float s[8][4];
#pragma unroll
        for (int nt = 0; nt < 8; nt++)
#pragma unroll
            for (int r = 0; r < 4; r++) s[nt][r] = 0.f;
#pragma unroll
        for (int ks = 0; ks < 4; ks++) {
#pragma unroll
            for (int ntp = 0; ntp < 4; ntp++) {
                uint32_t r[4];
                ldsm4(r, kb + ((ntp * 16 + brow) * KSTR + ks * 16 + bcol) * 2);
                mma_f16(s[2 * ntp],     qf[ks], r,     s[2 * ntp]);
                mma_f16(s[2 * ntp + 1], qf[ks], r + 2, s[2 * ntp + 1]);
            }
        }

        float mx0 = -1e30f, mx1 = -1e30f;
#pragma unroll
        for (int nt = 0; nt < 8; nt++) {
            mx0 = fmaxf(mx0, fmaxf(s[nt][0], s[nt][1]));
            mx1 = fmaxf(mx1, fmaxf(s[nt][2], s[nt][3]));
        }
        mx0 = fmaxf(mx0, __shfl_xor_sync(0xffffffffu, mx0, 1));
        mx0 = fmaxf(mx0, __shfl_xor_sync(0xffffffffu, mx0, 2));
        mx1 = fmaxf(mx1, __shfl_xor_sync(0xffffffffu, mx1, 1));
        mx1 = fmaxf(mx1, __shfl_xor_sync(0xffffffffu, mx1, 2));

        float nm0 = fmaxf(m0v, mx0), nm1 = fmaxf(m1v, mx1);
        float a0 = __expf(m0v - nm0), a1 = __expf(m1v - nm1);
        m0v = nm0; m1v = nm1;
        l0 *= a0; l1 *= a1;
#pragma unroll
        for (int nt = 0; nt < 8; nt++) {
            o[nt][0] *= a0; o[nt][1] *= a0;
            o[nt][2] *= a1; o[nt][3] *= a1;
        }
        float ps0 = 0.f, ps1 = 0.f;
#pragma unroll
        for (int nt = 0; nt < 8; nt++) {
            s[nt][0] = __expf(s[nt][0] - nm0);
            s[nt][1] = __expf(s[nt][1] - nm0);
            s[nt][2] = __expf(s[nt][2] - nm1);
            s[nt][3] = __expf(s[nt][3] - nm1);
            ps0 += s[nt][0] + s[nt][1];
            ps1 += s[nt][2] + s[nt][3];
        }
        ps0 += __shfl_xor_sync(0xffffffffu, ps0, 1);
        ps0 += __shfl_xor_sync(0xffffffffu, ps0, 2);
        ps1 += __shfl_xor_sync(0xffffffffu, ps1, 1);
        ps1 += __shfl_xor_sync(0xffffffffu, ps1, 2);
        l0 += ps0; l1 += ps1;

#pragma unroll
        for (int k2 = 0; k2 < 4; k2++) {
            uint32_t af[4];
            af[0] = h2u(__floats2half2_rn(s[2 * k2][0],     s[2 * k2][1]));
            af[1] = h2u(__floats2half2_rn(s[2 * k2][2],     s[2 * k2][3]));
            af[2] = h2u(__floats2half2_rn(s[2 * k2 + 1][0], s[2 * k2 + 1][1]));
            af[3] = h2u(__floats2half2_rn(s[2 * k2 + 1][2], s[2 * k2 + 1][3]));
#pragma unroll
            for (int ntp = 0; ntp < 4; ntp++) {
                uint32_t r[4];
                ldsm4t(r, vb + ((k2 * 16 + vrow) * KSTR + ntp * 16 + vcol) * 2);
                mma_f16(o[2 * ntp],     af, r,     o[2 * ntp]);
                mma_f16(o[2 * ntp + 1], af, r + 2, o[2 * ntp + 1]);
            }
        }
        __syncthreads();
    }

    float inv0 = 1.f / l0, inv1 = 1.f / l1;
    __half* o0 = outh + (size_t)(b * N_ + qrow) * C_ + h * HD_;
    __half* o1 = o0 + (size_t)8 * C_;
#pragma unroll
    for (int nt = 0; nt < 8; nt++) {
        int c = nt * 8 + 2 * q;
        *(half2*)(o0 + c) = __floats2half2_rn(o[nt][0] * inv0, o[nt][1] * inv0);
        *(half2*)(o1 + c) = __floats2half2_rn(o[nt][2] * inv1, o[nt][3] * inv1);
    }
}

// ============================================================
// Launch orchestration
// ============================================================
extern "C" void kernel_launch(void* const* d_in, const int* in_sizes, int n_in,
                              void* d_out, int out_size) {
    const float* x      = (const float*)d_in[0];
    const float* w_qkv  = (const float*)d_in[1];
    const float* w_proj = (const float*)d_in[2];
    const float* b_proj = (const float*)d_in[3];
    const float* g1     = (const float*)d_in[4];
    const float* beta1  = (const float*)d_in[5];
    const float* g2     = (const float*)d_in[6];
    const float* beta2  = (const float*)d_in[7];
    const float* w_fc1  = (const float*)d_in[8];
    const float* b_fc1  = (const float*)d_in[9];
    const float* w_fc2  = (const float*)d_in[10];
    const float* b_fc2  = (const float*)d_in[11];
    const float* cos_x  = (const float*)d_in[12];
    const float* sin_x  = (const float*)d_in[13];
    const float* cos_y  = (const float*)d_in[14];
    const float* sin_y  = (const float*)d_in[15];
    float* out = (float*)d_out;

    __half *xnh, *qkvh, *attnh, *hh, *wqkvh, *wprojh, *wfc1h, *wfc2h;
    float* x1;
    cudaGetSymbolAddress((void**)&xnh,   g_xnh);
    cudaGetSymbolAddress((void**)&qkvh,  g_qkvh);
    cudaGetSymbolAddress((void**)&attnh, g_attnh);
    cudaGetSymbolAddress((void**)&x1,    g_x1);
    cudaGetSymbolAddress((void**)&hh,    g_hh);
    cudaGetSymbolAddress((void**)&wqkvh, g_wqkvh);
    cudaGetSymbolAddress((void**)&wprojh, g_wprojh);
    cudaGetSymbolAddress((void**)&wfc1h, g_wfc1h);
    cudaGetSymbolAddress((void**)&wfc2h, g_wfc2h);

    cudaFuncSetAttribute(gemm_h<0, 1, 1>, cudaFuncAttributeMaxDynamicSharedMemorySize, SMEM_GEMM);
    cudaFuncSetAttribute(gemm_h<0, 1, 0>, cudaFuncAttributeMaxDynamicSharedMemorySize, SMEM_GEMM);
    cudaFuncSetAttribute(gemm_h<0, 0, 0>, cudaFuncAttributeMaxDynamicSharedMemorySize, SMEM_GEMM);
    cudaFuncSetAttribute(gemm_h<1, 1, 0>, cudaFuncAttributeMaxDynamicSharedMemorySize, SMEM_GEMM);

    // weight conversions (single launch)
    f2h_all<<<(N8_TOT + 255) / 256, 256>>>(w_qkv, w_proj, w_fc1, w_fc2,
                                           wqkvh, wprojh, wfc1h, wfc2h);

    // 1. LN1 -> half
    ln_h<<<M_, 256>>>(x, g1, beta1, xnh);
    // 2. QKV projection + fused 2D RoPE -> half
    gemm_h<0, 1, 1><<<dim3(QKVD / 256, M_ / 128), 256, SMEM_GEMM>>>(
        xnh, wqkvh, nullptr, nullptr, qkvh, M_, QKVD, C_, cos_x, sin_x, cos_y, sin_y);
    // 3. Attention -> half
    attn_h<<<dim3(N_ / 128, B_ * H_), 256>>>(qkvh, attnh);
    // 4. proj + bias + residual(x) -> x1 (fp32)
    gemm_h<0, 0, 0><<<dim3(C_ / 256, M_ / 128), 256, SMEM_GEMM>>>(
        attnh, wprojh, b_proj, x, x1, M_, C_, C_, nullptr, nullptr, nullptr, nullptr);
    // 5. LN2 -> half
    ln_h<<<M_, 256>>>(x1, g2, beta2, xnh);
    // 6. FC1 + bias + GELU -> half
    gemm_h<1, 1, 0><<<dim3(4 * C_ / 256, M_ / 128), 256, SMEM_GEMM>>>(
        xnh, wfc1h, b_fc1, nullptr, hh, M_, 4 * C_, C_, nullptr, nullptr, nullptr, nullptr);
    // 7. FC2 + bias + residual(x1) -> out (fp32)
    gemm_h<0, 0, 0><<<dim3(C_ / 256, M_ / 128), 256, SMEM_GEMM>>>(
        hh, wfc2h, b_fc2, x1, out, M_, C_, 4 * C_, nullptr, nullptr, nullptr, nullptr);
}

// round 6
// speedup vs baseline: 7.6848x; 1.1657x over previous
#include <cuda_runtime.h>
#include <cuda_fp16.h>
#include <cstdint>
#include <cstddef>

constexpr int B_ = 2, N_ = 3072, C_ = 768, H_ = 12, HD_ = 64;
constexpr int M_ = B_ * N_;           // 6144
constexpr int QKVD = 3 * C_;          // 2304

// ---- static scratch ----
__device__ __half g_xnh[M_ * C_];
__device__ __half g_qkvh[(size_t)M_ * QKVD];
__device__ __half g_attnh[M_ * C_];
__device__ float  g_x1[M_ * C_];
__device__ __half g_hh[(size_t)M_ * 4 * C_];
__device__ __half g_wqkvh[QKVD * C_];
__device__ __half g_wprojh[C_ * C_];
__device__ __half g_wfc1h[4 * C_ * C_];
__device__ __half g_wfc2h[C_ * 4 * C_];

// ---- ptx helpers ----
__device__ __forceinline__ void mma_f16(float* d, const uint32_t* a,
                                        const uint32_t* b, const float* c) {
    asm volatile(
        "mma.sync.aligned.m16n8k16.row.col.f32.f16.f16.f32 "
        "{%0,%1,%2,%3},{%4,%5,%6,%7},{%8,%9},{%10,%11,%12,%13};"
        : "=f"(d[0]), "=f"(d[1]), "=f"(d[2]), "=f"(d[3])
        : "r"(a[0]), "r"(a[1]), "r"(a[2]), "r"(a[3]),
          "r"(b[0]), "r"(b[1]),
          "f"(c[0]), "f"(c[1]), "f"(c[2]), "f"(c[3]));
}
__device__ __forceinline__ void ldsm4(uint32_t* r, uint32_t a) {
    asm volatile("ldmatrix.sync.aligned.m8n8.x4.shared.b16 {%0,%1,%2,%3}, [%4];"
                 : "=r"(r[0]), "=r"(r[1]), "=r"(r[2]), "=r"(r[3]) : "r"(a));
}
__device__ __forceinline__ void ldsm4t(uint32_t* r, uint32_t a) {
    asm volatile("ldmatrix.sync.aligned.m8n8.x4.trans.shared.b16 {%0,%1,%2,%3}, [%4];"
                 : "=r"(r[0]), "=r"(r[1]), "=r"(r[2]), "=r"(r[3]) : "r"(a));
}
__device__ __forceinline__ void cpa16(uint32_t dst, const void* src) {
    asm volatile("cp.async.cg.shared.global [%0], [%1], 16;\n" :: "r"(dst), "l"(src));
}
#define CP_COMMIT() asm volatile("cp.async.commit_group;\n" ::: "memory")
#define CP_WAIT1()  asm volatile("cp.async.wait_group 1;\n" ::: "memory")

__device__ __forceinline__ uint32_t h2u(half2 h) { return *(uint32_t*)&h; }

// pack (lo,hi) f32 -> f16x2 then exp2 in f16x2 (one MUFU for two values)
__device__ __forceinline__ uint32_t exp2_h2(float lo, float hi) {
    uint32_t u;
    asm("{.reg .b32 t;\n\t"
        "cvt.rn.f16x2.f32 t, %2, %1;\n\t"
        "ex2.approx.f16x2 %0, t;}"
        : "=r"(u) : "f"(lo), "f"(hi));
    return u;
}

// ============================================================
// fused fp32 -> fp16 conversion for all 4 weight matrices
// ============================================================
constexpr int N8_QKV = QKVD * C_ / 8;
constexpr int N8_PRJ = C_ * C_ / 8;
constexpr int N8_FC  = 4 * C_ * C_ / 8;
constexpr int N8_TOT = N8_QKV + N8_PRJ + 2 * N8_FC;

__global__ void f2h_all(const float* __restrict__ s0, const float* __restrict__ s1,
                        const float* __restrict__ s2, const float* __restrict__ s3,
                        __half* __restrict__ d0, __half* __restrict__ d1,
                        __half* __restrict__ d2, __half* __restrict__ d3) {
    int i = blockIdx.x * blockDim.x + threadIdx.x;
    if (i >= N8_TOT) return;
    const float* s; __half* d;
    if (i < N8_QKV)                       { s = s0; d = d0; }
    else if (i < N8_QKV + N8_PRJ)         { s = s1; d = d1; i -= N8_QKV; }
    else if (i < N8_QKV + N8_PRJ + N8_FC) { s = s2; d = d2; i -= N8_QKV + N8_PRJ; }
    else                                  { s = s3; d = d3; i -= N8_QKV + N8_PRJ + N8_FC; }
    const float4* sp = (const float4*)s;
    float4 a = sp[2 * i], b = sp[2 * i + 1];
    half2 h[4] = {__floats2half2_rn(a.x, a.y), __floats2half2_rn(a.z, a.w),
                  __floats2half2_rn(b.x, b.y), __floats2half2_rn(b.z, b.w)};
    ((uint4*)d)[i] = *(uint4*)h;
}

// ============================================================
// LayerNorm -> half output
// ============================================================
__global__ void ln_h(const float* __restrict__ x, const float* __restrict__ g,
                     const float* __restrict__ b, __half* __restrict__ out) {
    int row = blockIdx.x;
    int tid = threadIdx.x;
    const float* xr = x + (size_t)row * C_;
    float v[3];
    float s = 0.f, sq = 0.f;
#pragma unroll
    for (int i = 0; i < 3; i++) {
        v[i] = xr[tid + i * 256];
        s += v[i];
        sq += v[i] * v[i];
    }
#pragma unroll
    for (int o = 16; o > 0; o >>= 1) {
        s  += __shfl_xor_sync(0xffffffffu, s, o);
        sq += __shfl_xor_sync(0xffffffffu, sq, o);
    }
    __shared__ float ws[8], wq[8];
    int wid = tid >> 5, lid = tid & 31;
    if (lid == 0) { ws[wid] = s; wq[wid] = sq; }
    __syncthreads();
    if (tid == 0) {
        float ts = 0.f, tq = 0.f;
#pragma unroll
        for (int i = 0; i < 8; i++) { ts += ws[i]; tq += wq[i]; }
        float mean = ts * (1.0f / C_);
        float var  = tq * (1.0f / C_) - mean * mean;
        ws[0] = mean;
        wq[0] = rsqrtf(var + 1e-5f);
    }
    __syncthreads();
    float mean = ws[0], rstd = wq[0];
    __half* orow = out + (size_t)row * C_;
#pragma unroll
    for (int i = 0; i < 3; i++) {
        int c = tid + i * 256;
        orow[c] = __float2half_rn((v[i] - mean) * rstd * g[c] + b[c]);
    }
}

// ============================================================
// fp16 tensor-core GEMM NT: 128x128x32 block, 4 warps (2x2),
// warp tile 64x64, 3-stage cp.async, 2 blocks/SM.
// ROPE=1: fused 2D rope on q/k sections of QKV output (OUTH=1).
// ============================================================
constexpr int ASTR = 40;
constexpr int A_STG = 128 * ASTR;          // halves per stage (A and W alike)
constexpr int SMEM_GEMM = 3 * 2 * A_STG * 2;   // 61440 bytes

template <int ACT, int OUTH, int ROPE>
__global__ void __launch_bounds__(128, 2)
gemm_h(const __half* __restrict__ A, const __half* __restrict__ W,
       const float* __restrict__ bias, const float* __restrict__ resid,
       void* __restrict__ Cout, int M, int Nd, int K,
       const float* __restrict__ cx, const float* __restrict__ sx,
       const float* __restrict__ cy, const float* __restrict__ sy)
{
    extern __shared__ __half sm[];
    __half* As = sm;                    // 3 stages of 128x32 (stride 40)
    __half* Ws = sm + 3 * A_STG;

    const int tid = threadIdx.x, lane = tid & 31, wid = tid >> 5;
    const int warpM = wid >> 1, warpN = wid & 1;
    const int g = lane >> 2, q = lane & 3;
    const int m0 = blockIdx.y * 128, n0 = blockIdx.x * 128;

    const uint32_t asbase = (uint32_t)__cvta_generic_to_shared(As);
    const uint32_t wsbase = (uint32_t)__cvta_generic_to_shared(Ws);

    auto stage = [&](int t, int s) {
        int k0 = t * 32;
        uint32_t ab = asbase + s * (A_STG * 2);
        uint32_t wb = wsbase + s * (A_STG * 2);
#pragma unroll
        for (int i = 0; i < 4; i++) {
            int idx = tid + i * 128;
            int r = idx >> 2, c = (idx & 3) * 8;
            cpa16(ab + (r * ASTR + c) * 2, A + (size_t)(m0 + r) * K + k0 + c);
            cpa16(wb + (r * ASTR + c) * 2, W + (size_t)(n0 + r) * K + k0 + c);
        }
    };

    float acc[4][8][4];
#pragma unroll
    for (int mt = 0; mt < 4; mt++)
#pragma unroll
        for (int nt = 0; nt < 8; nt++)
#pragma unroll
            for (int r = 0; r < 4; r++) acc[mt][nt][r] = 0.f;

    const int T = K / 32;
    stage(0, 0); CP_COMMIT();
    stage(1, 1); CP_COMMIT();

    const int lrow = warpM * 64 + (lane & 7) + ((lane >> 3) & 1) * 8;
    const int lcol = (lane >> 4) * 8;
    const int brow = (lane & 7) + ((lane >> 4) & 1) * 8;
    const int bcol = ((lane >> 3) & 1) * 8;

    for (int t = 0; t < T; t++) {
        CP_WAIT1();
        __syncthreads();
        if (t + 2 < T) stage(t + 2, (t + 2) % 3);
        CP_COMMIT();
        const int s = t % 3;
        const uint32_t ab = asbase + s * (A_STG * 2);
        const uint32_t wb = wsbase + s * (A_STG * 2);
#pragma unroll
        for (int kk = 0; kk < 32; kk += 16) {
            uint32_t af[4][4];
#pragma unroll
            for (int mt = 0; mt < 4; mt++)
                ldsm4(af[mt], ab + ((lrow + mt * 16) * ASTR + lcol + kk) * 2);
            uint32_t bf[8][2];
#pragma unroll
            for (int ntp = 0; ntp < 4; ntp++) {
                uint32_t r[4];
                ldsm4(r, wb + ((warpN * 64 + ntp * 16 + brow) * ASTR + kk + bcol) * 2);
                bf[2 * ntp][0] = r[0]; bf[2 * ntp][1] = r[1];
                bf[2 * ntp + 1][0] = r[2]; bf[2 * ntp + 1][1] = r[3];
            }
#pragma unroll
            for (int mt = 0; mt < 4; mt++)
#pragma unroll
                for (int nt = 0; nt < 8; nt++)
                    mma_f16(acc[mt][nt], af[mt], bf[nt], acc[mt][nt]);
        }
    }

    if (ROPE) {
        __half* O = (__half*)Cout;
        const int chunk = n0 + warpN * 64;          // 64-aligned = one head
        const bool qk = chunk < 2 * C_;
#pragma unroll
        for (int mt = 0; mt < 4; mt++) {
            int m = m0 + warpM * 64 + mt * 16 + g;
            int ntok = m % N_;
            if (qk) {
#pragma unroll
                for (int base = 0; base < 8; base += 4) {   // y half then x half
                    const float* ct = base ? cx : cy;
                    const float* st = base ? sx : sy;
#pragma unroll
                    for (int p = 0; p < 2; p++) {
                        int j = p * 8 + 2 * q;
                        float2 c0 = *(const float2*)&ct[ntok * 32 + j];
                        float2 s0 = *(const float2*)&st[ntok * 32 + j];
                        float2 c1 = *(const float2*)&ct[(ntok + 8) * 32 + j];
                        float2 s1 = *(const float2*)&st[(ntok + 8) * 32 + j];
                        float* lo = acc[mt][base + p];
                        float* hi = acc[mt][base + p + 2];
                        float t1, t2;
                        t1 = lo[0]; t2 = hi[0];
                        lo[0] = t1 * c0.x - t2 * s0.x; hi[0] = t2 * c0.x + t1 * s0.x;
                        t1 = lo[1]; t2 = hi[1];
                        lo[1] = t1 * c0.y - t2 * s0.y; hi[1] = t2 * c0.y + t1 * s0.y;
                        t1 = lo[2]; t2 = hi[2];
                        lo[2] = t1 * c1.x - t2 * s1.x; hi[2] = t2 * c1.x + t1 * s1.x;
                        t1 = lo[3]; t2 = hi[3];
                        lo[3] = t1 * c1.y - t2 * s1.y; hi[3] = t2 * c1.y + t1 * s1.y;
                    }
                }
            }
#pragma unroll
            for (int nt = 0; nt < 8; nt++) {
                int c = chunk + nt * 8 + 2 * q;
                size_t i0 = (size_t)m * Nd + c, i1 = (size_t)(m + 8) * Nd + c;
                *(half2*)(O + i0) = __floats2half2_rn(acc[mt][nt][0], acc[mt][nt][1]);
                *(half2*)(O + i1) = __floats2half2_rn(acc[mt][nt][2], acc[mt][nt][3]);
            }
        }
        return;
    }

#pragma unroll
    for (int mt = 0; mt < 4; mt++) {
#pragma unroll
        for (int nt = 0; nt < 8; nt++) {
            int m = m0 + warpM * 64 + mt * 16 + g;
            int c = n0 + warpN * 64 + nt * 8 + 2 * q;
            float bv0 = bias ? bias[c] : 0.f;
            float bv1 = bias ? bias[c + 1] : 0.f;
            float v0 = acc[mt][nt][0] + bv0, v1 = acc[mt][nt][1] + bv1;
            float v2 = acc[mt][nt][2] + bv0, v3 = acc[mt][nt][3] + bv1;
            if (ACT == 1) {
                v0 = 0.5f * v0 * (1.0f + erff(v0 * 0.70710678118654752f));
                v1 = 0.5f * v1 * (1.0f + erff(v1 * 0.70710678118654752f));
                v2 = 0.5f * v2 * (1.0f + erff(v2 * 0.70710678118654752f));
                v3 = 0.5f * v3 * (1.0f + erff(v3 * 0.70710678118654752f));
            }
            size_t i0 = (size_t)m * Nd + c, i1 = (size_t)(m + 8) * Nd + c;
            if (OUTH) {
                __half* O = (__half*)Cout;
                *(half2*)(O + i0) = __floats2half2_rn(v0, v1);
                *(half2*)(O + i1) = __floats2half2_rn(v2, v3);
            } else {
                float* O = (float*)Cout;
                if (resid) {
                    float2 r0 = *(const float2*)&resid[i0];
                    float2 r1 = *(const float2*)&resid[i1];
                    v0 += r0.x; v1 += r0.y; v2 += r1.x; v3 += r1.y;
                }
                *(float2*)&O[i0] = make_float2(v0, v1);
                *(float2*)&O[i1] = make_float2(v2, v3);
            }
        }
    }
}

// ============================================================
// Flash attention fp16 mma, 128 q-rows/block (8 warps),
// exp2-domain softmax: f16x2 EX2 + mma row-sum (no shuffles/packs).
// ============================================================
constexpr int KSTR = 72;

__global__ void __launch_bounds__(256)
attn_h(const __half* __restrict__ qkvh, __half* __restrict__ outh)
{
    __shared__ __half Ks[2][64 * KSTR];
    __shared__ __half Vs[2][64 * KSTR];

    const int tid = threadIdx.x, lane = tid & 31, wid = tid >> 5;
    const int g = lane >> 2, q = lane & 3;
    const int bh = blockIdx.y, b = bh / H_, h = bh % H_;
    const int qrow = blockIdx.x * 128 + wid * 16 + g;

    const uint32_t ksbase = (uint32_t)__cvta_generic_to_shared(&Ks[0][0]);
    const uint32_t vsbase = (uint32_t)__cvta_generic_to_shared(&Vs[0][0]);

    const int brow = (lane & 7) + ((lane >> 4) & 1) * 8;
    const int bcol = ((lane >> 3) & 1) * 8;
    const int vrow = (lane & 7) + ((lane >> 3) & 1) * 8;
    const int vcol = ((lane >> 4) & 1) * 8;

    // Q fragments scaled by HD^-0.5 * log2(e)  -> S in exp2 domain
    uint32_t qf[4][4];
    {
        const __half* q0 = qkvh + (size_t)(b * N_ + qrow) * QKVD + h * HD_;
        const __half* q1 = q0 + (size_t)8 * QKVD;
        const half2 sc = __float2half2_rn(0.125f * 1.44269504088896341f);
#pragma unroll
        for (int ks = 0; ks < 4; ks++) {
            int col = ks * 16 + 2 * q;
            qf[ks][0] = h2u(__hmul2(*(const half2*)(q0 + col), sc));
            qf[ks][1] = h2u(__hmul2(*(const half2*)(q1 + col), sc));
            qf[ks][2] = h2u(__hmul2(*(const half2*)(q0 + col + 8), sc));
            qf[ks][3] = h2u(__hmul2(*(const half2*)(q1 + col + 8), sc));
        }
    }

    const size_t kgbase = (size_t)(b * N_) * QKVD + C_ + h * HD_;
    const size_t vgbase = kgbase + C_;

    auto stage = [&](int kt, int buf) {
#pragma unroll
        for (int i = 0; i < 2; i++) {
            int idx = tid + i * 256;
            int r = idx >> 3, c = idx & 7;
            size_t roff = (size_t)(kt + r) * QKVD + c * 8;
            cpa16(ksbase + (buf * 64 * KSTR + r * KSTR + c * 8) * 2, qkvh + kgbase + roff);
            cpa16(vsbase + (buf * 64 * KSTR + r * KSTR + c * 8) * 2, qkvh + vgbase + roff);
        }
    };

    float o[8][4];
#pragma unroll
    for (int nt = 0; nt < 8; nt++)
#pragma unroll
        for (int r = 0; r < 4; r++) o[nt][r] = 0.f;
    float m0v = -1e30f, m1v = -1e30f, l0 = 0.f, l1 = 0.f;

    const uint32_t ones2[2] = {0x3C003C00u, 0x3C003C00u};  // half2(1,1) x2

    stage(0, 0); CP_COMMIT();

    constexpr int T = N_ / 64;
    for (int t = 0; t < T; t++) {
        if (t + 1 < T) stage((t + 1) * 64, (t + 1) & 1);
        CP_COMMIT();
        CP_WAIT1();
        __syncthreads();

        const uint32_t kb = ksbase + (t & 1) * (64 * KSTR * 2);
        const uint32_t vb = vsbase + (t & 1) * (64 * KSTR * 2);

        // S = Q K^T  (exp2 domain)
        float s[8][4];
#pragma unroll
        for (int nt = 0; nt < 8; nt++)
#pragma unroll
            for (int r = 0; r < 4; r++) s[nt][r] = 0.f;
#pragma unroll
        for (int ks = 0; ks < 4; ks++) {
#pragma unroll
            for (int ntp = 0; ntp < 4; ntp++) {
                uint32_t r[4];
                ldsm4(r, kb + ((ntp * 16 + brow) * KSTR + ks * 16 + bcol) * 2);
                mma_f16(s[2 * ntp],     qf[ks], r,     s[2 * ntp]);
                mma_f16(s[2 * ntp + 1], qf[ks], r + 2, s[2 * ntp + 1]);
            }
        }

        // running max (quad reduction)
        float mx0 = -1e30f, mx1 = -1e30f;
#pragma unroll
        for (int nt = 0; nt < 8; nt++) {
            mx0 = fmaxf(mx0, fmaxf(s[nt][0], s[nt][1]));
            mx1 = fmaxf(mx1, fmaxf(s[nt][2], s[nt][3]));
        }
        mx0 = fmaxf(mx0, __shfl_xor_sync(0xffffffffu, mx0, 1));
        mx0 = fmaxf(mx0, __shfl_xor_sync(0xffffffffu, mx0, 2));
        mx1 = fmaxf(mx1, __shfl_xor_sync(0xffffffffu, mx1, 1));
        mx1 = fmaxf(mx1, __shfl_xor_sync(0xffffffffu, mx1, 2));

        float nm0 = fmaxf(m0v, mx0), nm1 = fmaxf(m1v, mx1);
        float a0 = exp2f(m0v - nm0), a1 = exp2f(m1v - nm1);
        m0v = nm0; m1v = nm1;
#pragma unroll
        for (int nt = 0; nt < 8; nt++) {
            o[nt][0] *= a0; o[nt][1] *= a0;
            o[nt][2] *= a1; o[nt][3] *= a1;
        }

        // P = exp2(S - m) directly as half2 fragments
        uint32_t pf[8][2];
#pragma unroll
        for (int nt = 0; nt < 8; nt++) {
            pf[nt][0] = exp2_h2(s[nt][0] - nm0, s[nt][1] - nm0);
            pf[nt][1] = exp2_h2(s[nt][2] - nm1, s[nt][3] - nm1);
        }

        // O += P V  and row-sum via mma with ones
        float fs[4] = {0.f, 0.f, 0.f, 0.f};
#pragma unroll
        for (int k2 = 0; k2 < 4; k2++) {
            uint32_t af[4] = {pf[2 * k2][0], pf[2 * k2][1],
                              pf[2 * k2 + 1][0], pf[2 * k2 + 1][1]};
            mma_f16(fs, af, ones2, fs);
#pragma unroll
            for (int ntp = 0; ntp < 4; ntp++) {
                uint32_t r[4];
                ldsm4t(r, vb + ((k2 * 16 + vrow) * KSTR + ntp * 16 + vcol) * 2);
                mma_f16(o[2 * ntp],     af, r,     o[2 * ntp]);
                mma_f16(o[2 * ntp + 1], af, r + 2, o[2 * ntp + 1]);
            }
        }
        l0 = l0 * a0 + fs[0];
        l1 = l1 * a1 + fs[2];
        __syncthreads();
    }

    float inv0 = 1.f / l0, inv1 = 1.f / l1;
    __half* o0 = outh + (size_t)(b * N_ + qrow) * C_ + h * HD_;
    __half* o1 = o0 + (size_t)8 * C_;
#pragma unroll
    for (int nt = 0; nt < 8; nt++) {
        int c = nt * 8 + 2 * q;
        *(half2*)(o0 + c) = __floats2half2_rn(o[nt][0] * inv0, o[nt][1] * inv0);
        *(half2*)(o1 + c) = __floats2half2_rn(o[nt][2] * inv1, o[nt][3] * inv1);
    }
}

// ============================================================
// Launch orchestration
// ============================================================
extern "C" void kernel_launch(void* const* d_in, const int* in_sizes, int n_in,
                              void* d_out, int out_size) {
    const float* x      = (const float*)d_in[0];
    const float* w_qkv  = (const float*)d_in[1];
    const float* w_proj = (const float*)d_in[2];
    const float* b_proj = (const float*)d_in[3];
    const float* g1     = (const float*)d_in[4];
    const float* beta1  = (const float*)d_in[5];
    const float* g2     = (const float*)d_in[6];
    const float* beta2  = (const float*)d_in[7];
    const float* w_fc1  = (const float*)d_in[8];
    const float* b_fc1  = (const float*)d_in[9];
    const float* w_fc2  = (const float*)d_in[10];
    const float* b_fc2  = (const float*)d_in[11];
    const float* cos_x  = (const float*)d_in[12];
    const float* sin_x  = (const float*)d_in[13];
    const float* cos_y  = (const float*)d_in[14];
    const float* sin_y  = (const float*)d_in[15];
    float* out = (float*)d_out;

    __half *xnh, *qkvh, *attnh, *hh, *wqkvh, *wprojh, *wfc1h, *wfc2h;
    float* x1;
    cudaGetSymbolAddress((void**)&xnh,   g_xnh);
    cudaGetSymbolAddress((void**)&qkvh,  g_qkvh);
    cudaGetSymbolAddress((void**)&attnh, g_attnh);
    cudaGetSymbolAddress((void**)&x1,    g_x1);
    cudaGetSymbolAddress((void**)&hh,    g_hh);
    cudaGetSymbolAddress((void**)&wqkvh, g_wqkvh);
    cudaGetSymbolAddress((void**)&wprojh, g_wprojh);
    cudaGetSymbolAddress((void**)&wfc1h, g_wfc1h);
    cudaGetSymbolAddress((void**)&wfc2h, g_wfc2h);

    cudaFuncSetAttribute(gemm_h<0, 1, 1>, cudaFuncAttributeMaxDynamicSharedMemorySize, SMEM_GEMM);
    cudaFuncSetAttribute(gemm_h<0, 0, 0>, cudaFuncAttributeMaxDynamicSharedMemorySize, SMEM_GEMM);
    cudaFuncSetAttribute(gemm_h<1, 1, 0>, cudaFuncAttributeMaxDynamicSharedMemorySize, SMEM_GEMM);

    // weight conversions (single launch)
    f2h_all<<<(N8_TOT + 255) / 256, 256>>>(w_qkv, w_proj, w_fc1, w_fc2,
                                           wqkvh, wprojh, wfc1h, wfc2h);

    // 1. LN1 -> half
    ln_h<<<M_, 256>>>(x, g1, beta1, xnh);
    // 2. QKV projection + fused 2D RoPE -> half
    gemm_h<0, 1, 1><<<dim3(QKVD / 128, M_ / 128), 128, SMEM_GEMM>>>(
        xnh, wqkvh, nullptr, nullptr, qkvh, M_, QKVD, C_, cos_x, sin_x, cos_y, sin_y);
    // 3. Attention -> half
    attn_h<<<dim3(N_ / 128, B_ * H_), 256>>>(qkvh, attnh);
    // 4. proj + bias + residual(x) -> x1 (fp32)
    gemm_h<0, 0, 0><<<dim3(C_ / 128, M_ / 128), 128, SMEM_GEMM>>>(
        attnh, wprojh, b_proj, x, x1, M_, C_, C_, nullptr, nullptr, nullptr, nullptr);
    // 5. LN2 -> half
    ln_h<<<M_, 256>>>(x1, g2, beta2, xnh);
    // 6. FC1 + bias + GELU -> half
    gemm_h<1, 1, 0><<<dim3(4 * C_ / 128, M_ / 128), 128, SMEM_GEMM>>>(
        xnh, wfc1h, b_fc1, nullptr, hh, M_, 4 * C_, C_, nullptr, nullptr, nullptr, nullptr);
    // 7. FC2 + bias + residual(x1) -> out (fp32)
    gemm_h<0, 0, 0><<<dim3(C_ / 128, M_ / 128), 128, SMEM_GEMM>>>(
        hh, wfc2h, b_fc2, x1, out, M_, C_, 4 * C_, nullptr, nullptr, nullptr, nullptr);
}